// round 11
// baseline (speedup 1.0000x reference)
#include <cuda_runtime.h>
#include <cuda_bf16.h>
#include <cstdint>

// Problem constants
#define BB 4
#define SS 2048
#define DD 1024
#define MM 4

// GEMM tiling: CTA 128x128, BK=32, 8 warps (64x32 warp tile), 3-stage, XOR swizzle
#define BM 128
#define BN 128
#define BK 32
#define TILE_B 8192                       // 128 rows x 64 bytes, unpadded
#define STAGE_B (4 * TILE_B)              // Ah | Al | Bh | Bl = 32768
#define NSTAGE 3
#define GEMM_SMEM_BYTES (NSTAGE * STAGE_B)   // 98304 -> 2 CTA/SM

// XOR swizzle: 16B chunk index ^= (row>>1)&3  (conflict-free per 8-row ldsm phase)
__device__ __forceinline__ uint32_t swz(int row, int halfoff) {
    return (uint32_t)(row * 64) + (uint32_t)((((halfoff >> 3) ^ ((row >> 1) & 3)) << 4));
}

// ---------------------------------------------------------------------------
// Scratch (__device__ globals; allocation-free rule)
// ---------------------------------------------------------------------------
__device__ __align__(256) __nv_bfloat16 g_xh[BB * SS * DD];
__device__ __align__(256) __nv_bfloat16 g_xl[BB * SS * DD];
__device__ __align__(256) __nv_bfloat16 g_Wqth[DD * DD], g_Wqtl[DD * DD];
__device__ __align__(256) __nv_bfloat16 g_Wkth[DD * DD], g_Wktl[DD * DD];
__device__ __align__(256) __nv_bfloat16 g_Wvth[DD * DD], g_Wvtl[DD * DD];
__device__ __align__(256) __nv_bfloat16 g_Woth[DD * DD], g_Wotl[DD * DD];
__device__ __align__(256) __nv_bfloat16 g_Qh[BB * SS * DD], g_Ql[BB * SS * DD];
__device__ __align__(256) __nv_bfloat16 g_Kh[BB * SS * DD], g_Kl[BB * SS * DD];
__device__ __align__(256) float         g_Vf[BB * SS * DD];
__device__ __align__(256) __nv_bfloat16 g_Vth[BB * DD * SS], g_Vtl[BB * DD * SS];
__device__ __align__(256) float         g_S[(long long)BB * SS * SS];
__device__ __align__(256) __nv_bfloat16 g_Sh[(long long)BB * SS * SS], g_Sl[(long long)BB * SS * SS];
__device__ __align__(256) __nv_bfloat16 g_Ath[BB * SS * DD], g_Atl[BB * SS * DD];

// ---------------------------------------------------------------------------
// PTX helpers
// ---------------------------------------------------------------------------
__device__ __forceinline__ void cp_async16(uint32_t saddr, const void* gptr) {
    asm volatile("cp.async.cg.shared.global [%0], [%1], 16;\n" :: "r"(saddr), "l"(gptr));
}
__device__ __forceinline__ void cp_commit() {
    asm volatile("cp.async.commit_group;\n");
}
__device__ __forceinline__ void cp_wait2() {
    asm volatile("cp.async.wait_group 2;\n");
}
__device__ __forceinline__ void ldsm4(uint32_t* r, uint32_t saddr) {
    asm volatile("ldmatrix.sync.aligned.m8n8.x4.shared.b16 {%0,%1,%2,%3}, [%4];\n"
                 : "=r"(r[0]), "=r"(r[1]), "=r"(r[2]), "=r"(r[3]) : "r"(saddr));
}
__device__ __forceinline__ void mma_bf16(float* c, const uint32_t* a, const uint32_t* b) {
    asm volatile(
        "mma.sync.aligned.m16n8k16.row.col.f32.bf16.bf16.f32 "
        "{%0,%1,%2,%3}, {%4,%5,%6,%7}, {%8,%9}, {%0,%1,%2,%3};\n"
        : "+f"(c[0]), "+f"(c[1]), "+f"(c[2]), "+f"(c[3])
        : "r"(a[0]), "r"(a[1]), "r"(a[2]), "r"(a[3]), "r"(b[0]), "r"(b[1]));
}

// ---------------------------------------------------------------------------
// 3-term split-bf16 GEMM: C = scale * (A @ B^T-logical) (+ bias)
//   A given as Ah+Al, bf16, row-major [M][K] (k-major)
//   B given as Bh+Bl, bf16, [N][K] (k-major)
//   computes Ah*Bh + Ah*Bl + Al*Bh with f32 accumulation
// EPI = 0: C fp32 [M][N].  EPI = 1: write bf16 hi/lo pair arrays [M][N].
// M,N multiples of 128; K multiple of 32. Batched via blockIdx.z.
// ---------------------------------------------------------------------------
template <int EPI, bool BIAS>
__global__ void __launch_bounds__(256) gemm3_kernel(
    const __nv_bfloat16* __restrict__ Ah, const __nv_bfloat16* __restrict__ Al,
    const __nv_bfloat16* __restrict__ Bh, const __nv_bfloat16* __restrict__ Bl,
    const float* __restrict__ bias,
    float* __restrict__ C, __nv_bfloat16* __restrict__ Chi, __nv_bfloat16* __restrict__ Clo,
    int Mdim, int Ndim, int Kdim, float scale,
    long long sA, long long sB, long long sC)
{
    Ah += (long long)blockIdx.z * sA;  Al += (long long)blockIdx.z * sA;
    Bh += (long long)blockIdx.z * sB;  Bl += (long long)blockIdx.z * sB;
    if (EPI == 0) C += (long long)blockIdx.z * sC;
    else { Chi += (long long)blockIdx.z * sC; Clo += (long long)blockIdx.z * sC; }

    extern __shared__ __align__(128) __nv_bfloat16 smem[];
    const uint32_t smem_u32 = (uint32_t)__cvta_generic_to_shared(smem);

    const int tid  = threadIdx.x;
    const int lane = tid & 31;
    const int warp = tid >> 5;
    const int wm = warp >> 2;      // 0..1  (64-row slabs)
    const int wn = warp & 3;       // 0..3  (32-col slabs)
    const int m0 = blockIdx.y * BM;
    const int n0 = blockIdx.x * BN;

    // ldmatrix lane-derived offsets
    const int aRow = lane & 15;
    const int aK   = (lane >> 4) << 3;                       // 0 or 8
    const int bRow = (((lane >> 4) & 1) << 3) + (lane & 7);  // n within 16
    const int bK   = ((lane >> 3) & 1) << 3;                 // 0 or 8

    float acc[4][4][4];
#pragma unroll
    for (int i = 0; i < 4; i++)
#pragma unroll
        for (int j = 0; j < 4; j++)
#pragma unroll
            for (int c = 0; c < 4; c++) acc[i][j][c] = 0.f;

    const int tiles = Kdim / BK;

    // stage loader: 4 operand tiles, 128 rows x 32 halves each, XOR-swizzled
    auto load_stage = [&](int st, int k0) {
        uint32_t sbase = smem_u32 + (uint32_t)(st * STAGE_B);
#pragma unroll
        for (int p = 0; p < 2; p++) {
            int idx = tid + p * 256;
            int row = idx >> 2;
            int ck  = idx & 3;          // 16B chunk 0..3
            int kc  = ck << 3;          // half offset 0/8/16/24
            long long ga = (long long)(m0 + row) * Kdim + k0 + kc;
            long long gb = (long long)(n0 + row) * Kdim + k0 + kc;
            uint32_t so = swz(row, kc);
            cp_async16(sbase + 0 * TILE_B + so, Ah + ga);
            cp_async16(sbase + 1 * TILE_B + so, Al + ga);
            cp_async16(sbase + 2 * TILE_B + so, Bh + gb);
            cp_async16(sbase + 3 * TILE_B + so, Bl + gb);
        }
    };

    load_stage(0, 0);
    cp_commit();
    load_stage(1, BK);
    cp_commit();

    for (int t = 0; t < tiles; ++t) {
        if (t + 2 < tiles) load_stage((t + 2) % 3, (t + 2) * BK);
        cp_commit();                 // empty group on tail iters keeps accounting right
        cp_wait2();                  // stage t resident (t+1, t+2 may be in flight)
        __syncthreads();

        const uint32_t sbase = smem_u32 + (uint32_t)((t % 3) * STAGE_B);
        const uint32_t sAh = sbase;
        const uint32_t sAl = sbase + 1u * TILE_B;
        const uint32_t sBh = sbase + 2u * TILE_B;
        const uint32_t sBl = sbase + 3u * TILE_B;

#pragma unroll
        for (int k16 = 0; k16 < 2; ++k16) {
            const int kb = k16 * 16;
            uint32_t a[4][4], bh[4][2], bl[4][2];

            // B hi / lo fragments (2 x ldmatrix.x4 each cover 2 n-octets)
#pragma unroll
            for (int h = 0; h < 2; h++) {
                uint32_t off = swz(wn * 32 + h * 16 + bRow, kb + bK);
                uint32_t r[4];
                ldsm4(r, sBh + off);
                bh[2 * h][0] = r[0]; bh[2 * h][1] = r[1];
                bh[2 * h + 1][0] = r[2]; bh[2 * h + 1][1] = r[3];
                ldsm4(r, sBl + off);
                bl[2 * h][0] = r[0]; bl[2 * h][1] = r[1];
                bl[2 * h + 1][0] = r[2]; bl[2 * h + 1][1] = r[3];
            }

            // A hi fragments
#pragma unroll
            for (int mt = 0; mt < 4; mt++) {
                uint32_t off = swz(wm * 64 + mt * 16 + aRow, kb + aK);
                ldsm4(a[mt], sAh + off);
            }
            // pass 1: Ah * Bh
#pragma unroll
            for (int mt = 0; mt < 4; mt++)
#pragma unroll
                for (int nt = 0; nt < 4; nt++) mma_bf16(acc[mt][nt], a[mt], bh[nt]);
            // pass 2: Ah * Bl
#pragma unroll
            for (int mt = 0; mt < 4; mt++)
#pragma unroll
                for (int nt = 0; nt < 4; nt++) mma_bf16(acc[mt][nt], a[mt], bl[nt]);

            // A lo fragments (reuse regs)
#pragma unroll
            for (int mt = 0; mt < 4; mt++) {
                uint32_t off = swz(wm * 64 + mt * 16 + aRow, kb + aK);
                ldsm4(a[mt], sAl + off);
            }
            // pass 3: Al * Bh
#pragma unroll
            for (int mt = 0; mt < 4; mt++)
#pragma unroll
                for (int nt = 0; nt < 4; nt++) mma_bf16(acc[mt][nt], a[mt], bh[nt]);
        }
        __syncthreads();
    }

    // Epilogue
    const int g  = lane >> 2;
    const int tg = lane & 3;
#pragma unroll
    for (int mt = 0; mt < 4; mt++) {
#pragma unroll
        for (int nt = 0; nt < 4; nt++) {
            int row = m0 + wm * 64 + mt * 16 + g;
            int col = n0 + wn * 32 + nt * 8 + tg * 2;
            float b0 = 0.f, b1 = 0.f;
            if (BIAS) { b0 = bias[col]; b1 = bias[col + 1]; }
            float v0 = acc[mt][nt][0] * scale + b0;
            float v1 = acc[mt][nt][1] * scale + b1;
            float v2 = acc[mt][nt][2] * scale + b0;
            float v3 = acc[mt][nt][3] * scale + b1;
            if (EPI == 0) {
                float2* p0 = reinterpret_cast<float2*>(C + (long long)row * Ndim + col);
                float2* p1 = reinterpret_cast<float2*>(C + (long long)(row + 8) * Ndim + col);
                *p0 = make_float2(v0, v1);
                *p1 = make_float2(v2, v3);
            } else {
                __nv_bfloat16 h0 = __float2bfloat16_rn(v0);
                __nv_bfloat16 h1 = __float2bfloat16_rn(v1);
                __nv_bfloat16 h2 = __float2bfloat16_rn(v2);
                __nv_bfloat16 h3 = __float2bfloat16_rn(v3);
                __nv_bfloat16 l0 = __float2bfloat16_rn(v0 - __bfloat162float(h0));
                __nv_bfloat16 l1 = __float2bfloat16_rn(v1 - __bfloat162float(h1));
                __nv_bfloat16 l2 = __float2bfloat16_rn(v2 - __bfloat162float(h2));
                __nv_bfloat16 l3 = __float2bfloat16_rn(v3 - __bfloat162float(h3));
                *reinterpret_cast<__nv_bfloat162*>(Chi + (long long)row * Ndim + col)       = __nv_bfloat162(h0, h1);
                *reinterpret_cast<__nv_bfloat162*>(Chi + (long long)(row + 8) * Ndim + col) = __nv_bfloat162(h2, h3);
                *reinterpret_cast<__nv_bfloat162*>(Clo + (long long)row * Ndim + col)       = __nv_bfloat162(l0, l1);
                *reinterpret_cast<__nv_bfloat162*>(Clo + (long long)(row + 8) * Ndim + col) = __nv_bfloat162(l2, l3);
            }
        }
    }
}

// ---------------------------------------------------------------------------
// fp32 -> bf16 hi/lo elementwise split (row-major, vectorized by 4)
// ---------------------------------------------------------------------------
__global__ void __launch_bounds__(256) split_kernel(
    const float* __restrict__ src, __nv_bfloat16* __restrict__ hi,
    __nv_bfloat16* __restrict__ lo, long long n)
{
    long long i = ((long long)blockIdx.x * 256 + threadIdx.x) * 4;
    if (i >= n) return;
    float4 v = *reinterpret_cast<const float4*>(src + i);
    __nv_bfloat16 h0 = __float2bfloat16_rn(v.x), h1 = __float2bfloat16_rn(v.y);
    __nv_bfloat16 h2 = __float2bfloat16_rn(v.z), h3 = __float2bfloat16_rn(v.w);
    __nv_bfloat16 l0 = __float2bfloat16_rn(v.x - __bfloat162float(h0));
    __nv_bfloat16 l1 = __float2bfloat16_rn(v.y - __bfloat162float(h1));
    __nv_bfloat16 l2 = __float2bfloat16_rn(v.z - __bfloat162float(h2));
    __nv_bfloat16 l3 = __float2bfloat16_rn(v.w - __bfloat162float(h3));
    __nv_bfloat162* ph = reinterpret_cast<__nv_bfloat162*>(hi + i);
    __nv_bfloat162* pl = reinterpret_cast<__nv_bfloat162*>(lo + i);
    ph[0] = __nv_bfloat162(h0, h1); ph[1] = __nv_bfloat162(h2, h3);
    pl[0] = __nv_bfloat162(l0, l1); pl[1] = __nv_bfloat162(l2, l3);
}

// ---------------------------------------------------------------------------
// fp32 [R][C] -> transposed bf16 hi/lo [C][R] (batched via z)
// ---------------------------------------------------------------------------
__global__ void __launch_bounds__(256) split_transpose_kernel(
    const float* __restrict__ src, __nv_bfloat16* __restrict__ hi,
    __nv_bfloat16* __restrict__ lo, int R, int C)
{
    __shared__ float t[32][33];
    const long long inb  = (long long)blockIdx.z * R * C;
    const long long outb = (long long)blockIdx.z * C * R;
    const int tx = threadIdx.x, ty = threadIdx.y;
    const int r0 = blockIdx.y * 32, c0 = blockIdx.x * 32;

#pragma unroll
    for (int j = 0; j < 4; j++)
        t[ty + j * 8][tx] = src[inb + (long long)(r0 + ty + j * 8) * C + c0 + tx];
    __syncthreads();
#pragma unroll
    for (int j = 0; j < 4; j++) {
        float v = t[tx][ty + j * 8];
        __nv_bfloat16 h = __float2bfloat16_rn(v);
        __nv_bfloat16 l = __float2bfloat16_rn(v - __bfloat162float(h));
        long long o = outb + (long long)(c0 + ty + j * 8) * R + r0 + tx;
        hi[o] = h; lo[o] = l;
    }
}

// ---------------------------------------------------------------------------
// Fast exp on the FMA pipe (no MUFU). Valid for softmax args (x <= 0); rel err ~2e-6.
// ---------------------------------------------------------------------------
__device__ __forceinline__ float fast_exp(float x) {
    float y = x * 1.4426950408889634f;
    y = fmaxf(y, -126.0f);
    float t = y + 12582912.0f;                    // round-to-nearest integer
    int   ni = __float_as_int(t) - 0x4B400000;    // = lrint(y)
    float f = y - (t - 12582912.0f);              // f in [-0.5, 0.5]
    float p = 1.3333558146e-3f;
    p = fmaf(p, f, 9.6181291076e-3f);
    p = fmaf(p, f, 5.5504108664e-2f);
    p = fmaf(p, f, 2.4022650696e-1f);
    p = fmaf(p, f, 6.9314718056e-1f);
    p = fmaf(p, f, 1.0f);
    return __int_as_float(__float_as_int(p) + (ni << 23));
}

// ---------------------------------------------------------------------------
// Fused multi-mask softmax combine: reads fp32 scores, writes bf16 hi/lo
// combined weights directly.
// ---------------------------------------------------------------------------
__device__ __forceinline__ float warpMax(float v) {
#pragma unroll
    for (int o = 16; o > 0; o >>= 1) v = fmaxf(v, __shfl_xor_sync(0xffffffffu, v, o));
    return v;
}
__device__ __forceinline__ float warpSum(float v) {
#pragma unroll
    for (int o = 16; o > 0; o >>= 1) v += __shfl_xor_sync(0xffffffffu, v, o);
    return v;
}

__global__ void __launch_bounds__(256) softmax_combine_kernel(
    const int* __restrict__ masks, const float* __restrict__ Sc,
    __nv_bfloat16* __restrict__ Wh, __nv_bfloat16* __restrict__ Wl)
{
    const int q   = blockIdx.x;
    const int tid = threadIdx.x;
    const int wid = tid >> 5;
    const int lid = tid & 31;

    __shared__ float         Erow[SS];
    __shared__ unsigned char mrow[MM][SS];
    __shared__ float         mred[8];
    __shared__ float         zred[8][MM];

#pragma unroll
    for (int m = 0; m < MM; m++) {
        const int* mp = masks + ((long long)m * SS + q) * SS;
        for (int k = tid; k < SS; k += 256) mrow[m][k] = (unsigned char)mp[k];
    }
    __syncthreads();

    for (int b = 0; b < BB; b++) {
        const float* srow = Sc + ((long long)b * SS + q) * SS;
        __nv_bfloat16* hrow = Wh + ((long long)b * SS + q) * SS;
        __nv_bfloat16* lrow = Wl + ((long long)b * SS + q) * SS;

        float mx = -1e30f;
        for (int k = tid; k < SS; k += 256) {
            float v = srow[k];
            Erow[k] = v;
            mx = fmaxf(mx, v);
        }
        mx = warpMax(mx);
        if (lid == 0) mred[wid] = mx;
        __syncthreads();
        mx = mred[0];
#pragma unroll
        for (int w = 1; w < 8; w++) mx = fmaxf(mx, mred[w]);

        float z[MM] = {0.f, 0.f, 0.f, 0.f};
        for (int k = tid; k < SS; k += 256) {
            float e = fast_exp(Erow[k] - mx);
            Erow[k] = e;
#pragma unroll
            for (int m = 0; m < MM; m++)
                if (mrow[m][k]) z[m] += e;
        }
#pragma unroll
        for (int m = 0; m < MM; m++) z[m] = warpSum(z[m]);
        if (lid == 0) {
#pragma unroll
            for (int m = 0; m < MM; m++) zred[wid][m] = z[m];
        }
        __syncthreads();
        float inv[MM];
#pragma unroll
        for (int m = 0; m < MM; m++) {
            float s = 0.f;
#pragma unroll
            for (int w = 0; w < 8; w++) s += zred[w][m];
            inv[m] = (1.0f / (float)MM) / s;   // fold the /M mean here
        }

        for (int k = tid; k < SS; k += 256) {
            float c = 0.f;
#pragma unroll
            for (int m = 0; m < MM; m++)
                if (mrow[m][k]) c += inv[m];
            float w = Erow[k] * c;
            __nv_bfloat16 h = __float2bfloat16_rn(w);
            hrow[k] = h;
            lrow[k] = __float2bfloat16_rn(w - __bfloat162float(h));
        }
        __syncthreads();
    }
}

// ---------------------------------------------------------------------------
extern "C" void kernel_launch(void* const* d_in, const int* in_sizes, int n_in,
                              void* d_out, int out_size)
{
    const float* x     = (const float*)d_in[0];
    const int*   masks = (const int*)  d_in[1];
    const float* Wq = (const float*)d_in[2]; const float* bq = (const float*)d_in[3];
    const float* Wk = (const float*)d_in[4]; const float* bk = (const float*)d_in[5];
    const float* Wv = (const float*)d_in[6]; const float* bv = (const float*)d_in[7];
    const float* Wo = (const float*)d_in[8]; const float* bo = (const float*)d_in[9];
    float* out = (float*)d_out;

    __nv_bfloat16 *xh, *xl, *Wqth, *Wqtl, *Wkth, *Wktl, *Wvth, *Wvtl, *Woth, *Wotl;
    __nv_bfloat16 *Qh, *Ql, *Kh, *Kl, *Vth, *Vtl, *Sh, *Sl, *Ath, *Atl;
    float *Vf, *Sc;
    cudaGetSymbolAddress((void**)&xh, g_xh);   cudaGetSymbolAddress((void**)&xl, g_xl);
    cudaGetSymbolAddress((void**)&Wqth, g_Wqth); cudaGetSymbolAddress((void**)&Wqtl, g_Wqtl);
    cudaGetSymbolAddress((void**)&Wkth, g_Wkth); cudaGetSymbolAddress((void**)&Wktl, g_Wktl);
    cudaGetSymbolAddress((void**)&Wvth, g_Wvth); cudaGetSymbolAddress((void**)&Wvtl, g_Wvtl);
    cudaGetSymbolAddress((void**)&Woth, g_Woth); cudaGetSymbolAddress((void**)&Wotl, g_Wotl);
    cudaGetSymbolAddress((void**)&Qh, g_Qh);   cudaGetSymbolAddress((void**)&Ql, g_Ql);
    cudaGetSymbolAddress((void**)&Kh, g_Kh);   cudaGetSymbolAddress((void**)&Kl, g_Kl);
    cudaGetSymbolAddress((void**)&Vf, g_Vf);
    cudaGetSymbolAddress((void**)&Vth, g_Vth); cudaGetSymbolAddress((void**)&Vtl, g_Vtl);
    cudaGetSymbolAddress((void**)&Sc, g_S);
    cudaGetSymbolAddress((void**)&Sh, g_Sh);   cudaGetSymbolAddress((void**)&Sl, g_Sl);
    cudaGetSymbolAddress((void**)&Ath, g_Ath); cudaGetSymbolAddress((void**)&Atl, g_Atl);

    cudaFuncSetAttribute(gemm3_kernel<0, false>, cudaFuncAttributeMaxDynamicSharedMemorySize, GEMM_SMEM_BYTES);
    cudaFuncSetAttribute(gemm3_kernel<0, true >, cudaFuncAttributeMaxDynamicSharedMemorySize, GEMM_SMEM_BYTES);
    cudaFuncSetAttribute(gemm3_kernel<1, false>, cudaFuncAttributeMaxDynamicSharedMemorySize, GEMM_SMEM_BYTES);
    cudaFuncSetAttribute(gemm3_kernel<1, true >, cudaFuncAttributeMaxDynamicSharedMemorySize, GEMM_SMEM_BYTES);

    const dim3 blk(256);
    const long long sdQKV = (long long)SS * DD;
    const long long sdS   = (long long)SS * SS;
    const long long sdVT  = (long long)DD * SS;

    // 0. Splits: x (row-major), weights (transposed so B is [n][k])
    {
        long long nx = (long long)BB * SS * DD;
        split_kernel<<<(unsigned)((nx / 4 + 255) / 256), blk>>>(x, xh, xl, nx);
        dim3 tg(DD / 32, DD / 32, 1), tb(32, 8);
        split_transpose_kernel<<<tg, tb>>>(Wq, Wqth, Wqtl, DD, DD);
        split_transpose_kernel<<<tg, tb>>>(Wk, Wkth, Wktl, DD, DD);
        split_transpose_kernel<<<tg, tb>>>(Wv, Wvth, Wvtl, DD, DD);
        split_transpose_kernel<<<tg, tb>>>(Wo, Woth, Wotl, DD, DD);
    }

    // 1. Projections: Q,K emit bf16 hi/lo directly; V emits fp32 (needs transpose)
    {
        dim3 g(DD / BN, (BB * SS) / BM, 1);
        gemm3_kernel<1, true><<<g, blk, GEMM_SMEM_BYTES>>>(xh, xl, Wqth, Wqtl, bq,
            nullptr, Qh, Ql, BB * SS, DD, DD, 1.0f, 0, 0, 0);
        gemm3_kernel<1, true><<<g, blk, GEMM_SMEM_BYTES>>>(xh, xl, Wkth, Wktl, bk,
            nullptr, Kh, Kl, BB * SS, DD, DD, 1.0f, 0, 0, 0);
        gemm3_kernel<0, true><<<g, blk, GEMM_SMEM_BYTES>>>(xh, xl, Wvth, Wvtl, bv,
            Vf, nullptr, nullptr, BB * SS, DD, DD, 1.0f, 0, 0, 0);
    }

    // 2. V transpose-split: [B][S][D] fp32 -> [B][D][S] bf16 hi/lo
    {
        dim3 tg(DD / 32, SS / 32, BB), tb(32, 8);
        split_transpose_kernel<<<tg, tb>>>(Vf, Vth, Vtl, SS, DD);
    }

    // 3. Scores: Sc[b] = Q[b] @ K[b]^T / 32 (both operands k-major), fp32 out
    {
        dim3 g(SS / BN, SS / BM, BB);
        gemm3_kernel<0, false><<<g, blk, GEMM_SMEM_BYTES>>>(Qh, Ql, Kh, Kl, nullptr,
            Sc, nullptr, nullptr, SS, SS, DD, 0.03125f, sdQKV, sdQKV, sdS);
    }

    // 4. Multi-mask softmax combine -> bf16 hi/lo weights directly
    softmax_combine_kernel<<<SS, blk>>>(masks, Sc, Sh, Sl);

    // 5. attn[b] = W[b] @ V[b] : A=[q][k] W, B=[n=D][k=S] V^T -> bf16 hi/lo out
    {
        dim3 g(DD / BN, SS / BM, BB);
        gemm3_kernel<1, false><<<g, blk, GEMM_SMEM_BYTES>>>(Sh, Sl, Vth, Vtl, nullptr,
            nullptr, Ath, Atl, SS, DD, SS, 1.0f, sdS, sdVT, sdQKV);
    }

    // 6. out = attn @ Wo + bo
    {
        dim3 g(DD / BN, (BB * SS) / BM, 1);
        gemm3_kernel<0, true><<<g, blk, GEMM_SMEM_BYTES>>>(Ath, Atl, Woth, Wotl, bo,
            out, nullptr, nullptr, BB * SS, DD, DD, 1.0f, 0, 0, 0);
    }
}

// round 12
// speedup vs baseline: 1.0869x; 1.0869x over previous
#include <cuda_runtime.h>
#include <cuda_bf16.h>
#include <cstdint>

// Problem constants
#define BB 4
#define SS 2048
#define DD 1024
#define MM 4

// GEMM tiling (R9 proven): CTA 128x128, BK=32, 8 warps, 2-stage, SROW=40 pad
#define BM 128
#define BN 128
#define BK 32
#define SROW 40                 // halfwords per smem row (32 + 8 pad -> 80B)
#define TILEH (128 * SROW)      // halves per operand tile (10240 B)
#define NSTAGE 2
#define GEMM_SMEM_BYTES (NSTAGE * 4 * TILEH * 2)   // 81920

// ---------------------------------------------------------------------------
// Scratch (__device__ globals; allocation-free rule)
// ---------------------------------------------------------------------------
__device__ __align__(256) __nv_bfloat16 g_xh[BB * SS * DD], g_xl[BB * SS * DD];
__device__ __align__(256) __nv_bfloat16 g_Wqh[DD * DD], g_Wql[DD * DD];     // Wq row-major split
__device__ __align__(256) __nv_bfloat16 g_Wkh[DD * DD], g_Wkl[DD * DD];     // Wk row-major split
__device__ __align__(256) __nv_bfloat16 g_Wqkth[DD * DD], g_Wqktl[DD * DD]; // (Wk @ Wq^T) split
__device__ __align__(256) __nv_bfloat16 g_Wvth[DD * DD], g_Wvtl[DD * DD];
__device__ __align__(256) __nv_bfloat16 g_Woth[DD * DD], g_Wotl[DD * DD];
__device__ __align__(256) __nv_bfloat16 g_Ph[BB * SS * DD], g_Pl[BB * SS * DD];  // P = x*Wqk
__device__ __align__(256) float         g_Vf[BB * SS * DD];
__device__ __align__(256) __nv_bfloat16 g_Vth[BB * DD * SS], g_Vtl[BB * DD * SS];
__device__ __align__(256) float         g_S[(long long)BB * SS * SS];
__device__ __align__(256) __nv_bfloat16 g_Sh[(long long)BB * SS * SS], g_Sl[(long long)BB * SS * SS];
__device__ __align__(256) __nv_bfloat16 g_Ath[BB * SS * DD], g_Atl[BB * SS * DD];
__device__ __align__(256) float         g_wkbq[DD];        // Wk @ bq
__device__ __align__(256) float         g_tau[BB * SS];    // (x . wkbq)/32 per token

// ---------------------------------------------------------------------------
// PTX helpers
// ---------------------------------------------------------------------------
__device__ __forceinline__ void cp_async16(uint32_t saddr, const void* gptr) {
    asm volatile("cp.async.cg.shared.global [%0], [%1], 16;\n" :: "r"(saddr), "l"(gptr));
}
__device__ __forceinline__ void cp_commit() { asm volatile("cp.async.commit_group;\n"); }
__device__ __forceinline__ void cp_wait1()  { asm volatile("cp.async.wait_group 1;\n"); }
__device__ __forceinline__ void ldsm4(uint32_t* r, uint32_t saddr) {
    asm volatile("ldmatrix.sync.aligned.m8n8.x4.shared.b16 {%0,%1,%2,%3}, [%4];\n"
                 : "=r"(r[0]), "=r"(r[1]), "=r"(r[2]), "=r"(r[3]) : "r"(saddr));
}
__device__ __forceinline__ void mma_bf16(float* c, const uint32_t* a, const uint32_t* b) {
    asm volatile(
        "mma.sync.aligned.m16n8k16.row.col.f32.bf16.bf16.f32 "
        "{%0,%1,%2,%3}, {%4,%5,%6,%7}, {%8,%9}, {%0,%1,%2,%3};\n"
        : "+f"(c[0]), "+f"(c[1]), "+f"(c[2]), "+f"(c[3])
        : "r"(a[0]), "r"(a[1]), "r"(a[2]), "r"(a[3]), "r"(b[0]), "r"(b[1]));
}

// ---------------------------------------------------------------------------
// 3-term split-bf16 GEMM (R9 verbatim): C = scale * A @ B^T (+ bias)
// ---------------------------------------------------------------------------
template <int EPI, bool BIAS>
__global__ void __launch_bounds__(256) gemm3_kernel(
    const __nv_bfloat16* __restrict__ Ah, const __nv_bfloat16* __restrict__ Al,
    const __nv_bfloat16* __restrict__ Bh, const __nv_bfloat16* __restrict__ Bl,
    const float* __restrict__ bias,
    float* __restrict__ C, __nv_bfloat16* __restrict__ Chi, __nv_bfloat16* __restrict__ Clo,
    int Mdim, int Ndim, int Kdim, float scale,
    long long sA, long long sB, long long sC)
{
    Ah += (long long)blockIdx.z * sA;  Al += (long long)blockIdx.z * sA;
    Bh += (long long)blockIdx.z * sB;  Bl += (long long)blockIdx.z * sB;
    if (EPI == 0) C += (long long)blockIdx.z * sC;
    else { Chi += (long long)blockIdx.z * sC; Clo += (long long)blockIdx.z * sC; }

    extern __shared__ __align__(16) __nv_bfloat16 smem[];
    const uint32_t smem_u32 = (uint32_t)__cvta_generic_to_shared(smem);

    const int tid  = threadIdx.x;
    const int lane = tid & 31;
    const int warp = tid >> 5;
    const int wm = warp >> 2;
    const int wn = warp & 3;
    const int m0 = blockIdx.y * BM;
    const int n0 = blockIdx.x * BN;

    const int aRow = lane & 15;
    const int aK   = (lane >> 4) << 3;
    const int bRow = (((lane >> 4) & 1) << 3) + (lane & 7);
    const int bK   = ((lane >> 3) & 1) << 3;

    float acc[4][4][4];
#pragma unroll
    for (int i = 0; i < 4; i++)
#pragma unroll
        for (int j = 0; j < 4; j++)
#pragma unroll
            for (int c = 0; c < 4; c++) acc[i][j][c] = 0.f;

    const int tiles = Kdim / BK;

    auto load_stage = [&](int st, int k0) {
        uint32_t sbase = smem_u32 + (uint32_t)(st * 4 * TILEH * 2);
#pragma unroll
        for (int p = 0; p < 2; p++) {
            int idx = tid + p * 256;
            int row = idx >> 2;
            int kc  = (idx & 3) << 3;
            long long ga = (long long)(m0 + row) * Kdim + k0 + kc;
            long long gb = (long long)(n0 + row) * Kdim + k0 + kc;
            uint32_t so = (uint32_t)((row * SROW + kc) * 2);
            cp_async16(sbase + 0 * TILEH * 2 + so, Ah + ga);
            cp_async16(sbase + 1 * TILEH * 2 + so, Al + ga);
            cp_async16(sbase + 2 * TILEH * 2 + so, Bh + gb);
            cp_async16(sbase + 3 * TILEH * 2 + so, Bl + gb);
        }
    };

    load_stage(0, 0);
    cp_commit();

    for (int t = 0; t < tiles; ++t) {
        const int st = t & 1;
        if (t + 1 < tiles) load_stage(st ^ 1, (t + 1) * BK);
        cp_commit();
        cp_wait1();
        __syncthreads();

        const uint32_t sbase = smem_u32 + (uint32_t)(st * 4 * TILEH * 2);
        const uint32_t sAh = sbase;
        const uint32_t sAl = sbase + 1u * TILEH * 2;
        const uint32_t sBh = sbase + 2u * TILEH * 2;
        const uint32_t sBl = sbase + 3u * TILEH * 2;

#pragma unroll
        for (int k16 = 0; k16 < 2; ++k16) {
            const int kb = k16 * 16;
            uint32_t a[4][4], bh[4][2], bl[4][2];

#pragma unroll
            for (int h = 0; h < 2; h++) {
                uint32_t off = (uint32_t)(((wn * 32 + h * 16 + bRow) * SROW + kb + bK) * 2);
                uint32_t r[4];
                ldsm4(r, sBh + off);
                bh[2 * h][0] = r[0]; bh[2 * h][1] = r[1];
                bh[2 * h + 1][0] = r[2]; bh[2 * h + 1][1] = r[3];
                ldsm4(r, sBl + off);
                bl[2 * h][0] = r[0]; bl[2 * h][1] = r[1];
                bl[2 * h + 1][0] = r[2]; bl[2 * h + 1][1] = r[3];
            }

#pragma unroll
            for (int mt = 0; mt < 4; mt++) {
                uint32_t off = (uint32_t)(((wm * 64 + mt * 16 + aRow) * SROW + kb + aK) * 2);
                ldsm4(a[mt], sAh + off);
            }
#pragma unroll
            for (int mt = 0; mt < 4; mt++)
#pragma unroll
                for (int nt = 0; nt < 4; nt++) mma_bf16(acc[mt][nt], a[mt], bh[nt]);
#pragma unroll
            for (int mt = 0; mt < 4; mt++)
#pragma unroll
                for (int nt = 0; nt < 4; nt++) mma_bf16(acc[mt][nt], a[mt], bl[nt]);

#pragma unroll
            for (int mt = 0; mt < 4; mt++) {
                uint32_t off = (uint32_t)(((wm * 64 + mt * 16 + aRow) * SROW + kb + aK) * 2);
                ldsm4(a[mt], sAl + off);
            }
#pragma unroll
            for (int mt = 0; mt < 4; mt++)
#pragma unroll
                for (int nt = 0; nt < 4; nt++) mma_bf16(acc[mt][nt], a[mt], bh[nt]);
        }
        __syncthreads();
    }

    const int g  = lane >> 2;
    const int tg = lane & 3;
#pragma unroll
    for (int mt = 0; mt < 4; mt++) {
#pragma unroll
        for (int nt = 0; nt < 4; nt++) {
            int row = m0 + wm * 64 + mt * 16 + g;
            int col = n0 + wn * 32 + nt * 8 + tg * 2;
            float b0 = 0.f, b1 = 0.f;
            if (BIAS) { b0 = bias[col]; b1 = bias[col + 1]; }
            float v0 = acc[mt][nt][0] * scale + b0;
            float v1 = acc[mt][nt][1] * scale + b1;
            float v2 = acc[mt][nt][2] * scale + b0;
            float v3 = acc[mt][nt][3] * scale + b1;
            if (EPI == 0) {
                *reinterpret_cast<float2*>(C + (long long)row * Ndim + col)       = make_float2(v0, v1);
                *reinterpret_cast<float2*>(C + (long long)(row + 8) * Ndim + col) = make_float2(v2, v3);
            } else {
                __nv_bfloat16 h0 = __float2bfloat16_rn(v0);
                __nv_bfloat16 h1 = __float2bfloat16_rn(v1);
                __nv_bfloat16 h2 = __float2bfloat16_rn(v2);
                __nv_bfloat16 h3 = __float2bfloat16_rn(v3);
                __nv_bfloat16 l0 = __float2bfloat16_rn(v0 - __bfloat162float(h0));
                __nv_bfloat16 l1 = __float2bfloat16_rn(v1 - __bfloat162float(h1));
                __nv_bfloat16 l2 = __float2bfloat16_rn(v2 - __bfloat162float(h2));
                __nv_bfloat16 l3 = __float2bfloat16_rn(v3 - __bfloat162float(h3));
                *reinterpret_cast<__nv_bfloat162*>(Chi + (long long)row * Ndim + col)       = __nv_bfloat162(h0, h1);
                *reinterpret_cast<__nv_bfloat162*>(Chi + (long long)(row + 8) * Ndim + col) = __nv_bfloat162(h2, h3);
                *reinterpret_cast<__nv_bfloat162*>(Clo + (long long)row * Ndim + col)       = __nv_bfloat162(l0, l1);
                *reinterpret_cast<__nv_bfloat162*>(Clo + (long long)(row + 8) * Ndim + col) = __nv_bfloat162(l2, l3);
            }
        }
    }
}

// ---------------------------------------------------------------------------
// fp32 -> bf16 hi/lo elementwise split
// ---------------------------------------------------------------------------
__global__ void __launch_bounds__(256) split_kernel(
    const float* __restrict__ src, __nv_bfloat16* __restrict__ hi,
    __nv_bfloat16* __restrict__ lo, long long n)
{
    long long i = ((long long)blockIdx.x * 256 + threadIdx.x) * 4;
    if (i >= n) return;
    float4 v = *reinterpret_cast<const float4*>(src + i);
    __nv_bfloat16 h0 = __float2bfloat16_rn(v.x), h1 = __float2bfloat16_rn(v.y);
    __nv_bfloat16 h2 = __float2bfloat16_rn(v.z), h3 = __float2bfloat16_rn(v.w);
    __nv_bfloat16 l0 = __float2bfloat16_rn(v.x - __bfloat162float(h0));
    __nv_bfloat16 l1 = __float2bfloat16_rn(v.y - __bfloat162float(h1));
    __nv_bfloat16 l2 = __float2bfloat16_rn(v.z - __bfloat162float(h2));
    __nv_bfloat16 l3 = __float2bfloat16_rn(v.w - __bfloat162float(h3));
    __nv_bfloat162* ph = reinterpret_cast<__nv_bfloat162*>(hi + i);
    __nv_bfloat162* pl = reinterpret_cast<__nv_bfloat162*>(lo + i);
    ph[0] = __nv_bfloat162(h0, h1); ph[1] = __nv_bfloat162(h2, h3);
    pl[0] = __nv_bfloat162(l0, l1); pl[1] = __nv_bfloat162(l2, l3);
}

// ---------------------------------------------------------------------------
// fp32 [R][C] -> transposed bf16 hi/lo [C][R] (batched via z)
// ---------------------------------------------------------------------------
__global__ void __launch_bounds__(256) split_transpose_kernel(
    const float* __restrict__ src, __nv_bfloat16* __restrict__ hi,
    __nv_bfloat16* __restrict__ lo, int R, int C)
{
    __shared__ float t[32][33];
    const long long inb  = (long long)blockIdx.z * R * C;
    const long long outb = (long long)blockIdx.z * C * R;
    const int tx = threadIdx.x, ty = threadIdx.y;
    const int r0 = blockIdx.y * 32, c0 = blockIdx.x * 32;

#pragma unroll
    for (int j = 0; j < 4; j++)
        t[ty + j * 8][tx] = src[inb + (long long)(r0 + ty + j * 8) * C + c0 + tx];
    __syncthreads();
#pragma unroll
    for (int j = 0; j < 4; j++) {
        float v = t[tx][ty + j * 8];
        __nv_bfloat16 h = __float2bfloat16_rn(v);
        __nv_bfloat16 l = __float2bfloat16_rn(v - __bfloat162float(h));
        long long o = outb + (long long)(c0 + ty + j * 8) * R + r0 + tx;
        hi[o] = h; lo[o] = l;
    }
}

// ---------------------------------------------------------------------------
// Bias-correction GEMVs: wkbq = Wk @ bq ; tau = (x . wkbq) / 32
// ---------------------------------------------------------------------------
__global__ void __launch_bounds__(256) wkbq_kernel(
    const float* __restrict__ Wk, const float* __restrict__ bq, float* __restrict__ wkbq)
{
    const int warp = threadIdx.x >> 5, lane = threadIdx.x & 31;
    const int row = blockIdx.x * 8 + warp;          // d1
    if (row >= DD) return;
    const float* wrow = Wk + (long long)row * DD;
    float s = 0.f;
    for (int j = lane; j < DD; j += 32) s = fmaf(wrow[j], bq[j], s);
#pragma unroll
    for (int o = 16; o > 0; o >>= 1) s += __shfl_xor_sync(0xffffffffu, s, o);
    if (lane == 0) wkbq[row] = s;
}

__global__ void __launch_bounds__(256) tau_kernel(
    const float* __restrict__ x, const float* __restrict__ wkbq, float* __restrict__ tau)
{
    const int warp = threadIdx.x >> 5, lane = threadIdx.x & 31;
    const int row = blockIdx.x * 8 + warp;          // token index
    if (row >= BB * SS) return;
    const float* xrow = x + (long long)row * DD;
    float s = 0.f;
    for (int j = lane; j < DD; j += 32) s = fmaf(xrow[j], wkbq[j], s);
#pragma unroll
    for (int o = 16; o > 0; o >>= 1) s += __shfl_xor_sync(0xffffffffu, s, o);
    if (lane == 0) tau[row] = s * 0.03125f;         // fold 1/sqrt(D)
}

// ---------------------------------------------------------------------------
// Fast exp on the FMA pipe (no MUFU). Valid for softmax args (x <= 0).
// ---------------------------------------------------------------------------
__device__ __forceinline__ float fast_exp(float x) {
    float y = x * 1.4426950408889634f;
    y = fmaxf(y, -126.0f);
    float t = y + 12582912.0f;
    int   ni = __float_as_int(t) - 0x4B400000;
    float f = y - (t - 12582912.0f);
    float p = 1.3333558146e-3f;
    p = fmaf(p, f, 9.6181291076e-3f);
    p = fmaf(p, f, 5.5504108664e-2f);
    p = fmaf(p, f, 2.4022650696e-1f);
    p = fmaf(p, f, 6.9314718056e-1f);
    p = fmaf(p, f, 1.0f);
    return __int_as_float(__float_as_int(p) + (ni << 23));
}

// ---------------------------------------------------------------------------
// Fused multi-mask softmax combine: scores + tau (bias term), writes bf16 hi/lo
// ---------------------------------------------------------------------------
__device__ __forceinline__ float warpMax(float v) {
#pragma unroll
    for (int o = 16; o > 0; o >>= 1) v = fmaxf(v, __shfl_xor_sync(0xffffffffu, v, o));
    return v;
}
__device__ __forceinline__ float warpSum(float v) {
#pragma unroll
    for (int o = 16; o > 0; o >>= 1) v += __shfl_xor_sync(0xffffffffu, v, o);
    return v;
}

__global__ void __launch_bounds__(256) softmax_combine_kernel(
    const int* __restrict__ masks, const float* __restrict__ Sc,
    const float* __restrict__ tau,
    __nv_bfloat16* __restrict__ Wh, __nv_bfloat16* __restrict__ Wl)
{
    const int q   = blockIdx.x;
    const int tid = threadIdx.x;
    const int wid = tid >> 5;
    const int lid = tid & 31;

    __shared__ float         Erow[SS];
    __shared__ unsigned char mrow[MM][SS];
    __shared__ float         mred[8];
    __shared__ float         zred[8][MM];

#pragma unroll
    for (int m = 0; m < MM; m++) {
        const int* mp = masks + ((long long)m * SS + q) * SS;
        for (int k = tid; k < SS; k += 256) mrow[m][k] = (unsigned char)mp[k];
    }
    __syncthreads();

    for (int b = 0; b < BB; b++) {
        const float* srow = Sc + ((long long)b * SS + q) * SS;
        const float* trow = tau + (long long)b * SS;
        __nv_bfloat16* hrow = Wh + ((long long)b * SS + q) * SS;
        __nv_bfloat16* lrow = Wl + ((long long)b * SS + q) * SS;

        float mx = -1e30f;
        for (int k = tid; k < SS; k += 256) {
            float v = srow[k] + trow[k];
            Erow[k] = v;
            mx = fmaxf(mx, v);
        }
        mx = warpMax(mx);
        if (lid == 0) mred[wid] = mx;
        __syncthreads();
        mx = mred[0];
#pragma unroll
        for (int w = 1; w < 8; w++) mx = fmaxf(mx, mred[w]);

        float z[MM] = {0.f, 0.f, 0.f, 0.f};
        for (int k = tid; k < SS; k += 256) {
            float e = fast_exp(Erow[k] - mx);
            Erow[k] = e;
#pragma unroll
            for (int m = 0; m < MM; m++)
                if (mrow[m][k]) z[m] += e;
        }
#pragma unroll
        for (int m = 0; m < MM; m++) z[m] = warpSum(z[m]);
        if (lid == 0) {
#pragma unroll
            for (int m = 0; m < MM; m++) zred[wid][m] = z[m];
        }
        __syncthreads();
        float inv[MM];
#pragma unroll
        for (int m = 0; m < MM; m++) {
            float s = 0.f;
#pragma unroll
            for (int w = 0; w < 8; w++) s += zred[w][m];
            inv[m] = (1.0f / (float)MM) / s;
        }

        for (int k = tid; k < SS; k += 256) {
            float c = 0.f;
#pragma unroll
            for (int m = 0; m < MM; m++)
                if (mrow[m][k]) c += inv[m];
            float w = Erow[k] * c;
            __nv_bfloat16 h = __float2bfloat16_rn(w);
            hrow[k] = h;
            lrow[k] = __float2bfloat16_rn(w - __bfloat162float(h));
        }
        __syncthreads();
    }
}

// ---------------------------------------------------------------------------
extern "C" void kernel_launch(void* const* d_in, const int* in_sizes, int n_in,
                              void* d_out, int out_size)
{
    const float* x     = (const float*)d_in[0];
    const int*   masks = (const int*)  d_in[1];
    const float* Wq = (const float*)d_in[2]; const float* bq = (const float*)d_in[3];
    const float* Wk = (const float*)d_in[4]; /* bk unused: row-constant in softmax */
    const float* Wv = (const float*)d_in[6]; const float* bv = (const float*)d_in[7];
    const float* Wo = (const float*)d_in[8]; const float* bo = (const float*)d_in[9];
    float* out = (float*)d_out;

    __nv_bfloat16 *xh, *xl, *Wqh, *Wql, *Wkh, *Wkl, *Wqkth, *Wqktl;
    __nv_bfloat16 *Wvth, *Wvtl, *Woth, *Wotl;
    __nv_bfloat16 *Ph, *Pl, *Vth, *Vtl, *Sh, *Sl, *Ath, *Atl;
    float *Vf, *Sc, *wkbq, *tau;
    cudaGetSymbolAddress((void**)&xh, g_xh);       cudaGetSymbolAddress((void**)&xl, g_xl);
    cudaGetSymbolAddress((void**)&Wqh, g_Wqh);     cudaGetSymbolAddress((void**)&Wql, g_Wql);
    cudaGetSymbolAddress((void**)&Wkh, g_Wkh);     cudaGetSymbolAddress((void**)&Wkl, g_Wkl);
    cudaGetSymbolAddress((void**)&Wqkth, g_Wqkth); cudaGetSymbolAddress((void**)&Wqktl, g_Wqktl);
    cudaGetSymbolAddress((void**)&Wvth, g_Wvth);   cudaGetSymbolAddress((void**)&Wvtl, g_Wvtl);
    cudaGetSymbolAddress((void**)&Woth, g_Woth);   cudaGetSymbolAddress((void**)&Wotl, g_Wotl);
    cudaGetSymbolAddress((void**)&Ph, g_Ph);       cudaGetSymbolAddress((void**)&Pl, g_Pl);
    cudaGetSymbolAddress((void**)&Vf, g_Vf);
    cudaGetSymbolAddress((void**)&Vth, g_Vth);     cudaGetSymbolAddress((void**)&Vtl, g_Vtl);
    cudaGetSymbolAddress((void**)&Sc, g_S);
    cudaGetSymbolAddress((void**)&Sh, g_Sh);       cudaGetSymbolAddress((void**)&Sl, g_Sl);
    cudaGetSymbolAddress((void**)&Ath, g_Ath);     cudaGetSymbolAddress((void**)&Atl, g_Atl);
    cudaGetSymbolAddress((void**)&wkbq, g_wkbq);   cudaGetSymbolAddress((void**)&tau, g_tau);

    cudaFuncSetAttribute(gemm3_kernel<0, false>, cudaFuncAttributeMaxDynamicSharedMemorySize, GEMM_SMEM_BYTES);
    cudaFuncSetAttribute(gemm3_kernel<0, true >, cudaFuncAttributeMaxDynamicSharedMemorySize, GEMM_SMEM_BYTES);
    cudaFuncSetAttribute(gemm3_kernel<1, false>, cudaFuncAttributeMaxDynamicSharedMemorySize, GEMM_SMEM_BYTES);
    cudaFuncSetAttribute(gemm3_kernel<1, true >, cudaFuncAttributeMaxDynamicSharedMemorySize, GEMM_SMEM_BYTES);

    const dim3 blk(256);
    const long long sdQKV = (long long)SS * DD;
    const long long sdS   = (long long)SS * SS;
    const long long sdVT  = (long long)DD * SS;

    // 0. Splits + bias-correction GEMVs
    {
        long long nx = (long long)BB * SS * DD;
        split_kernel<<<(unsigned)((nx / 4 + 255) / 256), blk>>>(x, xh, xl, nx);
        long long nw = (long long)DD * DD;
        split_kernel<<<(unsigned)((nw / 4 + 255) / 256), blk>>>(Wq, Wqh, Wql, nw);   // row-major
        split_kernel<<<(unsigned)((nw / 4 + 255) / 256), blk>>>(Wk, Wkh, Wkl, nw);   // row-major
        dim3 tg(DD / 32, DD / 32, 1), tb(32, 8);
        split_transpose_kernel<<<tg, tb>>>(Wv, Wvth, Wvtl, DD, DD);
        split_transpose_kernel<<<tg, tb>>>(Wo, Woth, Wotl, DD, DD);
        wkbq_kernel<<<DD / 8, blk>>>(Wk, bq, wkbq);
        tau_kernel<<<(BB * SS) / 8, blk>>>(x, wkbq, tau);
    }

    // 1. Wqkt[d2][d1] = sum_j Wk[d2,j] * Wq[d1,j]  (= (Wq Wk^T)^T, B-operand of P)
    {
        dim3 g(DD / BN, DD / BM, 1);
        gemm3_kernel<1, false><<<g, blk, GEMM_SMEM_BYTES>>>(Wkh, Wkl, Wqh, Wql, nullptr,
            nullptr, Wqkth, Wqktl, DD, DD, DD, 1.0f, 0, 0, 0);
    }

    // 2. P = x @ Wqkt^T (no bias; bias terms handled by tau + row-invariance)
    {
        dim3 g(DD / BN, (BB * SS) / BM, 1);
        gemm3_kernel<1, false><<<g, blk, GEMM_SMEM_BYTES>>>(xh, xl, Wqkth, Wqktl, nullptr,
            nullptr, Ph, Pl, BB * SS, DD, DD, 1.0f, 0, 0, 0);
        // V projection (unchanged)
        gemm3_kernel<0, true><<<g, blk, GEMM_SMEM_BYTES>>>(xh, xl, Wvth, Wvtl, bv,
            Vf, nullptr, nullptr, BB * SS, DD, DD, 1.0f, 0, 0, 0);
    }

    // 3. V transpose-split: [B][S][D] fp32 -> [B][D][S] bf16 hi/lo
    {
        dim3 tg(DD / 32, SS / 32, BB), tb(32, 8);
        split_transpose_kernel<<<tg, tb>>>(Vf, Vth, Vtl, SS, DD);
    }

    // 4. Scores: Sc[b] = P[b] @ x[b]^T / 32  (B operand is x splits directly)
    {
        dim3 g(SS / BN, SS / BM, BB);
        gemm3_kernel<0, false><<<g, blk, GEMM_SMEM_BYTES>>>(Ph, Pl, xh, xl, nullptr,
            Sc, nullptr, nullptr, SS, SS, DD, 0.03125f, sdQKV, sdQKV, sdS);
    }

    // 5. Multi-mask softmax combine (adds tau) -> bf16 hi/lo weights
    softmax_combine_kernel<<<SS, blk>>>(masks, Sc, tau, Sh, Sl);

    // 6. attn[b] = W[b] @ V[b]
    {
        dim3 g(DD / BN, SS / BM, BB);
        gemm3_kernel<1, false><<<g, blk, GEMM_SMEM_BYTES>>>(Sh, Sl, Vth, Vtl, nullptr,
            nullptr, Ath, Atl, SS, DD, SS, 1.0f, sdS, sdVT, sdQKV);
    }

    // 7. out = attn @ Wo + bo
    {
        dim3 g(DD / BN, (BB * SS) / BM, 1);
        gemm3_kernel<0, true><<<g, blk, GEMM_SMEM_BYTES>>>(Ath, Atl, Woth, Wotl, bo,
            out, nullptr, nullptr, BB * SS, DD, DD, 1.0f, 0, 0, 0);
    }
}

// round 14
// speedup vs baseline: 1.2098x; 1.1131x over previous
#include <cuda_runtime.h>
#include <cuda_bf16.h>
#include <cstdint>

// Problem constants
#define BB 4
#define SS 2048
#define DD 1024
#define MM 4

// GEMM tiling (proven): CTA 128x128, BK=32, 8 warps, 2-stage, SROW=40 pad
#define BM 128
#define BN 128
#define BK 32
#define SROW 40                 // halfwords per smem row (32 + 8 pad -> 80B)
#define TILEH (128 * SROW)      // halves per operand tile (10240 B)
#define NSTAGE 2
#define GEMM_SMEM_BYTES (NSTAGE * 4 * TILEH * 2)   // 81920

// ---------------------------------------------------------------------------
// Scratch (__device__ globals; allocation-free rule)
// ---------------------------------------------------------------------------
__device__ __align__(256) __nv_bfloat16 g_xh[BB * SS * DD], g_xl[BB * SS * DD];
// small-GEMM combined operands: z=0 -> Wqkt inputs, z=1 -> Wvot inputs
__device__ __align__(256) __nv_bfloat16 g_sAh[2 * DD * DD], g_sAl[2 * DD * DD]; // [Wk ; Wo^T]
__device__ __align__(256) __nv_bfloat16 g_sBh[2 * DD * DD], g_sBl[2 * DD * DD]; // [Wq ; Wv]
__device__ __align__(256) __nv_bfloat16 g_sCh[2 * DD * DD], g_sCl[2 * DD * DD]; // [Wqkt ; Wvot]
__device__ __align__(256) __nv_bfloat16 g_Ph[BB * SS * DD], g_Pl[BB * SS * DD];  // P = x*Wqk
__device__ __align__(256) __nv_bfloat16 g_Vth[BB * DD * SS], g_Vtl[BB * DD * SS]; // (x Wvo)^T
__device__ __align__(256) float         g_S[(long long)BB * SS * SS];
__device__ __align__(256) __nv_bfloat16 g_Sh[(long long)BB * SS * SS], g_Sl[(long long)BB * SS * SS];
__device__ __align__(256) float         g_wkbq[DD];        // Wk @ bq
__device__ __align__(256) float         g_tau[BB * SS];    // (x . wkbq)/32 per token
__device__ __align__(256) float         g_cbias[DD];       // bv @ Wo + bo

// ---------------------------------------------------------------------------
// PTX helpers
// ---------------------------------------------------------------------------
__device__ __forceinline__ void cp_async16(uint32_t saddr, const void* gptr) {
    asm volatile("cp.async.cg.shared.global [%0], [%1], 16;\n" :: "r"(saddr), "l"(gptr));
}
__device__ __forceinline__ void cp_commit() { asm volatile("cp.async.commit_group;\n"); }
__device__ __forceinline__ void cp_wait1()  { asm volatile("cp.async.wait_group 1;\n"); }
__device__ __forceinline__ void ldsm4(uint32_t* r, uint32_t saddr) {
    asm volatile("ldmatrix.sync.aligned.m8n8.x4.shared.b16 {%0,%1,%2,%3}, [%4];\n"
                 : "=r"(r[0]), "=r"(r[1]), "=r"(r[2]), "=r"(r[3]) : "r"(saddr));
}
__device__ __forceinline__ void mma_bf16(float* c, const uint32_t* a, const uint32_t* b) {
    asm volatile(
        "mma.sync.aligned.m16n8k16.row.col.f32.bf16.bf16.f32 "
        "{%0,%1,%2,%3}, {%4,%5,%6,%7}, {%8,%9}, {%0,%1,%2,%3};\n"
        : "+f"(c[0]), "+f"(c[1]), "+f"(c[2]), "+f"(c[3])
        : "r"(a[0]), "r"(a[1]), "r"(a[2]), "r"(a[3]), "r"(b[0]), "r"(b[1]));
}

// ---------------------------------------------------------------------------
// 3-term split-bf16 GEMM (proven): C = scale * A @ B^T (+ bias)
//   A: Ah+Al bf16 [M][K] k-major.  B: Bh+Bl bf16 [N][K] k-major.
//   computes Ah*Bh + Ah*Bl + Al*Bh, fp32 accum.
// EPI=0: fp32 C.  EPI=1: bf16 hi/lo outputs.  Batched via blockIdx.z.
// ---------------------------------------------------------------------------
template <int EPI, bool BIAS>
__global__ void __launch_bounds__(256) gemm3_kernel(
    const __nv_bfloat16* __restrict__ Ah, const __nv_bfloat16* __restrict__ Al,
    const __nv_bfloat16* __restrict__ Bh, const __nv_bfloat16* __restrict__ Bl,
    const float* __restrict__ bias,
    float* __restrict__ C, __nv_bfloat16* __restrict__ Chi, __nv_bfloat16* __restrict__ Clo,
    int Mdim, int Ndim, int Kdim, float scale,
    long long sA, long long sB, long long sC)
{
    Ah += (long long)blockIdx.z * sA;  Al += (long long)blockIdx.z * sA;
    Bh += (long long)blockIdx.z * sB;  Bl += (long long)blockIdx.z * sB;
    if (EPI == 0) C += (long long)blockIdx.z * sC;
    else { Chi += (long long)blockIdx.z * sC; Clo += (long long)blockIdx.z * sC; }

    extern __shared__ __align__(16) __nv_bfloat16 smem[];
    const uint32_t smem_u32 = (uint32_t)__cvta_generic_to_shared(smem);

    const int tid  = threadIdx.x;
    const int lane = tid & 31;
    const int warp = tid >> 5;
    const int wm = warp >> 2;
    const int wn = warp & 3;
    const int m0 = blockIdx.y * BM;
    const int n0 = blockIdx.x * BN;

    const int aRow = lane & 15;
    const int aK   = (lane >> 4) << 3;
    const int bRow = (((lane >> 4) & 1) << 3) + (lane & 7);
    const int bK   = ((lane >> 3) & 1) << 3;

    float acc[4][4][4];
#pragma unroll
    for (int i = 0; i < 4; i++)
#pragma unroll
        for (int j = 0; j < 4; j++)
#pragma unroll
            for (int c = 0; c < 4; c++) acc[i][j][c] = 0.f;

    const int tiles = Kdim / BK;

    auto load_stage = [&](int st, int k0) {
        uint32_t sbase = smem_u32 + (uint32_t)(st * 4 * TILEH * 2);
#pragma unroll
        for (int p = 0; p < 2; p++) {
            int idx = tid + p * 256;
            int row = idx >> 2;
            int kc  = (idx & 3) << 3;
            long long ga = (long long)(m0 + row) * Kdim + k0 + kc;
            long long gb = (long long)(n0 + row) * Kdim + k0 + kc;
            uint32_t so = (uint32_t)((row * SROW + kc) * 2);
            cp_async16(sbase + 0 * TILEH * 2 + so, Ah + ga);
            cp_async16(sbase + 1 * TILEH * 2 + so, Al + ga);
            cp_async16(sbase + 2 * TILEH * 2 + so, Bh + gb);
            cp_async16(sbase + 3 * TILEH * 2 + so, Bl + gb);
        }
    };

    load_stage(0, 0);
    cp_commit();

    for (int t = 0; t < tiles; ++t) {
        const int st = t & 1;
        if (t + 1 < tiles) load_stage(st ^ 1, (t + 1) * BK);
        cp_commit();
        cp_wait1();
        __syncthreads();

        const uint32_t sbase = smem_u32 + (uint32_t)(st * 4 * TILEH * 2);
        const uint32_t sAh = sbase;
        const uint32_t sAl = sbase + 1u * TILEH * 2;
        const uint32_t sBh = sbase + 2u * TILEH * 2;
        const uint32_t sBl = sbase + 3u * TILEH * 2;

#pragma unroll
        for (int k16 = 0; k16 < 2; ++k16) {
            const int kb = k16 * 16;
            uint32_t a[4][4], bh[4][2], bl[4][2];

#pragma unroll
            for (int h = 0; h < 2; h++) {
                uint32_t off = (uint32_t)(((wn * 32 + h * 16 + bRow) * SROW + kb + bK) * 2);
                uint32_t r[4];
                ldsm4(r, sBh + off);
                bh[2 * h][0] = r[0]; bh[2 * h][1] = r[1];
                bh[2 * h + 1][0] = r[2]; bh[2 * h + 1][1] = r[3];
                ldsm4(r, sBl + off);
                bl[2 * h][0] = r[0]; bl[2 * h][1] = r[1];
                bl[2 * h + 1][0] = r[2]; bl[2 * h + 1][1] = r[3];
            }

#pragma unroll
            for (int mt = 0; mt < 4; mt++) {
                uint32_t off = (uint32_t)(((wm * 64 + mt * 16 + aRow) * SROW + kb + aK) * 2);
                ldsm4(a[mt], sAh + off);
            }
#pragma unroll
            for (int mt = 0; mt < 4; mt++)
#pragma unroll
                for (int nt = 0; nt < 4; nt++) mma_bf16(acc[mt][nt], a[mt], bh[nt]);
#pragma unroll
            for (int mt = 0; mt < 4; mt++)
#pragma unroll
                for (int nt = 0; nt < 4; nt++) mma_bf16(acc[mt][nt], a[mt], bl[nt]);

#pragma unroll
            for (int mt = 0; mt < 4; mt++) {
                uint32_t off = (uint32_t)(((wm * 64 + mt * 16 + aRow) * SROW + kb + aK) * 2);
                ldsm4(a[mt], sAl + off);
            }
#pragma unroll
            for (int mt = 0; mt < 4; mt++)
#pragma unroll
                for (int nt = 0; nt < 4; nt++) mma_bf16(acc[mt][nt], a[mt], bh[nt]);
        }
        __syncthreads();
    }

    const int g  = lane >> 2;
    const int tg = lane & 3;
#pragma unroll
    for (int mt = 0; mt < 4; mt++) {
#pragma unroll
        for (int nt = 0; nt < 4; nt++) {
            int row = m0 + wm * 64 + mt * 16 + g;
            int col = n0 + wn * 32 + nt * 8 + tg * 2;
            float b0 = 0.f, b1 = 0.f;
            if (BIAS) { b0 = bias[col]; b1 = bias[col + 1]; }
            float v0 = acc[mt][nt][0] * scale + b0;
            float v1 = acc[mt][nt][1] * scale + b1;
            float v2 = acc[mt][nt][2] * scale + b0;
            float v3 = acc[mt][nt][3] * scale + b1;
            if (EPI == 0) {
                *reinterpret_cast<float2*>(C + (long long)row * Ndim + col)       = make_float2(v0, v1);
                *reinterpret_cast<float2*>(C + (long long)(row + 8) * Ndim + col) = make_float2(v2, v3);
            } else {
                __nv_bfloat16 h0 = __float2bfloat16_rn(v0);
                __nv_bfloat16 h1 = __float2bfloat16_rn(v1);
                __nv_bfloat16 h2 = __float2bfloat16_rn(v2);
                __nv_bfloat16 h3 = __float2bfloat16_rn(v3);
                __nv_bfloat16 l0 = __float2bfloat16_rn(v0 - __bfloat162float(h0));
                __nv_bfloat16 l1 = __float2bfloat16_rn(v1 - __bfloat162float(h1));
                __nv_bfloat16 l2 = __float2bfloat16_rn(v2 - __bfloat162float(h2));
                __nv_bfloat16 l3 = __float2bfloat16_rn(v3 - __bfloat162float(h3));
                *reinterpret_cast<__nv_bfloat162*>(Chi + (long long)row * Ndim + col)       = __nv_bfloat162(h0, h1);
                *reinterpret_cast<__nv_bfloat162*>(Chi + (long long)(row + 8) * Ndim + col) = __nv_bfloat162(h2, h3);
                *reinterpret_cast<__nv_bfloat162*>(Clo + (long long)row * Ndim + col)       = __nv_bfloat162(l0, l1);
                *reinterpret_cast<__nv_bfloat162*>(Clo + (long long)(row + 8) * Ndim + col) = __nv_bfloat162(l2, l3);
            }
        }
    }
}

// ---------------------------------------------------------------------------
// fp32 -> bf16 hi/lo elementwise split
// ---------------------------------------------------------------------------
__global__ void __launch_bounds__(256) split_kernel(
    const float* __restrict__ src, __nv_bfloat16* __restrict__ hi,
    __nv_bfloat16* __restrict__ lo, long long n)
{
    long long i = ((long long)blockIdx.x * 256 + threadIdx.x) * 4;
    if (i >= n) return;
    float4 v = *reinterpret_cast<const float4*>(src + i);
    __nv_bfloat16 h0 = __float2bfloat16_rn(v.x), h1 = __float2bfloat16_rn(v.y);
    __nv_bfloat16 h2 = __float2bfloat16_rn(v.z), h3 = __float2bfloat16_rn(v.w);
    __nv_bfloat16 l0 = __float2bfloat16_rn(v.x - __bfloat162float(h0));
    __nv_bfloat16 l1 = __float2bfloat16_rn(v.y - __bfloat162float(h1));
    __nv_bfloat16 l2 = __float2bfloat16_rn(v.z - __bfloat162float(h2));
    __nv_bfloat16 l3 = __float2bfloat16_rn(v.w - __bfloat162float(h3));
    __nv_bfloat162* ph = reinterpret_cast<__nv_bfloat162*>(hi + i);
    __nv_bfloat162* pl = reinterpret_cast<__nv_bfloat162*>(lo + i);
    ph[0] = __nv_bfloat162(h0, h1); ph[1] = __nv_bfloat162(h2, h3);
    pl[0] = __nv_bfloat162(l0, l1); pl[1] = __nv_bfloat162(l2, l3);
}

// ---------------------------------------------------------------------------
// fp32 [R][C] -> transposed bf16 hi/lo [C][R]
// ---------------------------------------------------------------------------
__global__ void __launch_bounds__(256) split_transpose_kernel(
    const float* __restrict__ src, __nv_bfloat16* __restrict__ hi,
    __nv_bfloat16* __restrict__ lo, int R, int C)
{
    __shared__ float t[32][33];
    const long long inb  = (long long)blockIdx.z * R * C;
    const long long outb = (long long)blockIdx.z * C * R;
    const int tx = threadIdx.x, ty = threadIdx.y;
    const int r0 = blockIdx.y * 32, c0 = blockIdx.x * 32;

#pragma unroll
    for (int j = 0; j < 4; j++)
        t[ty + j * 8][tx] = src[inb + (long long)(r0 + ty + j * 8) * C + c0 + tx];
    __syncthreads();
#pragma unroll
    for (int j = 0; j < 4; j++) {
        float v = t[tx][ty + j * 8];
        __nv_bfloat16 h = __float2bfloat16_rn(v);
        __nv_bfloat16 l = __float2bfloat16_rn(v - __bfloat162float(h));
        long long o = outb + (long long)(c0 + ty + j * 8) * R + r0 + tx;
        hi[o] = h; lo[o] = l;
    }
}

// ---------------------------------------------------------------------------
// Bias helpers:
//   wkbq = Wk @ bq ; tau = (x . wkbq) / 32 ; cbias[d3] = sum_j bv[j]*Wo[j][d3] + bo[d3]
// ---------------------------------------------------------------------------
__global__ void __launch_bounds__(256) wkbq_kernel(
    const float* __restrict__ Wk, const float* __restrict__ bq, float* __restrict__ wkbq)
{
    const int warp = threadIdx.x >> 5, lane = threadIdx.x & 31;
    const int row = blockIdx.x * 8 + warp;
    if (row >= DD) return;
    const float* wrow = Wk + (long long)row * DD;
    float s = 0.f;
    for (int j = lane; j < DD; j += 32) s = fmaf(wrow[j], bq[j], s);
#pragma unroll
    for (int o = 16; o > 0; o >>= 1) s += __shfl_xor_sync(0xffffffffu, s, o);
    if (lane == 0) wkbq[row] = s;
}

__global__ void __launch_bounds__(256) tau_kernel(
    const float* __restrict__ x, const float* __restrict__ wkbq, float* __restrict__ tau)
{
    const int warp = threadIdx.x >> 5, lane = threadIdx.x & 31;
    const int row = blockIdx.x * 8 + warp;
    if (row >= BB * SS) return;
    const float* xrow = x + (long long)row * DD;
    float s = 0.f;
    for (int j = lane; j < DD; j += 32) s = fmaf(xrow[j], wkbq[j], s);
#pragma unroll
    for (int o = 16; o > 0; o >>= 1) s += __shfl_xor_sync(0xffffffffu, s, o);
    if (lane == 0) tau[row] = s * 0.03125f;
}

__global__ void __launch_bounds__(256) cbias_kernel(
    const float* __restrict__ bv, const float* __restrict__ Wo,
    const float* __restrict__ bo, float* __restrict__ cbias)
{
    const int d3 = blockIdx.x * 256 + threadIdx.x;
    if (d3 >= DD) return;
    float s = bo[d3];
    for (int j = 0; j < DD; j++) s = fmaf(bv[j], Wo[(long long)j * DD + d3], s);
    cbias[d3] = s;
}

// ---------------------------------------------------------------------------
// Fast exp on the FMA pipe (no MUFU). Valid for softmax args (x <= 0).
// ---------------------------------------------------------------------------
__device__ __forceinline__ float fast_exp(float x) {
    float y = x * 1.4426950408889634f;
    y = fmaxf(y, -126.0f);
    float t = y + 12582912.0f;
    int   ni = __float_as_int(t) - 0x4B400000;
    float f = y - (t - 12582912.0f);
    float p = 1.3333558146e-3f;
    p = fmaf(p, f, 9.6181291076e-3f);
    p = fmaf(p, f, 5.5504108664e-2f);
    p = fmaf(p, f, 2.4022650696e-1f);
    p = fmaf(p, f, 6.9314718056e-1f);
    p = fmaf(p, f, 1.0f);
    return __int_as_float(__float_as_int(p) + (ni << 23));
}

// ---------------------------------------------------------------------------
// Fused multi-mask softmax combine: scores + tau, writes bf16 hi/lo
// ---------------------------------------------------------------------------
__device__ __forceinline__ float warpMax(float v) {
#pragma unroll
    for (int o = 16; o > 0; o >>= 1) v = fmaxf(v, __shfl_xor_sync(0xffffffffu, v, o));
    return v;
}
__device__ __forceinline__ float warpSum(float v) {
#pragma unroll
    for (int o = 16; o > 0; o >>= 1) v += __shfl_xor_sync(0xffffffffu, v, o);
    return v;
}

__global__ void __launch_bounds__(256) softmax_combine_kernel(
    const int* __restrict__ masks, const float* __restrict__ Sc,
    const float* __restrict__ tau,
    __nv_bfloat16* __restrict__ Wh, __nv_bfloat16* __restrict__ Wl)
{
    const int q   = blockIdx.x;
    const int tid = threadIdx.x;
    const int wid = tid >> 5;
    const int lid = tid & 31;

    __shared__ float         Erow[SS];
    __shared__ unsigned char mrow[MM][SS];
    __shared__ float         mred[8];
    __shared__ float         zred[8][MM];

#pragma unroll
    for (int m = 0; m < MM; m++) {
        const int* mp = masks + ((long long)m * SS + q) * SS;
        for (int k = tid; k < SS; k += 256) mrow[m][k] = (unsigned char)mp[k];
    }
    __syncthreads();

    for (int b = 0; b < BB; b++) {
        const float* srow = Sc + ((long long)b * SS + q) * SS;
        const float* trow = tau + (long long)b * SS;
        __nv_bfloat16* hrow = Wh + ((long long)b * SS + q) * SS;
        __nv_bfloat16* lrow = Wl + ((long long)b * SS + q) * SS;

        float mx = -1e30f;
        for (int k = tid; k < SS; k += 256) {
            float v = srow[k] + trow[k];
            Erow[k] = v;
            mx = fmaxf(mx, v);
        }
        mx = warpMax(mx);
        if (lid == 0) mred[wid] = mx;
        __syncthreads();
        mx = mred[0];
#pragma unroll
        for (int w = 1; w < 8; w++) mx = fmaxf(mx, mred[w]);

        float z[MM] = {0.f, 0.f, 0.f, 0.f};
        for (int k = tid; k < SS; k += 256) {
            float e = fast_exp(Erow[k] - mx);
            Erow[k] = e;
#pragma unroll
            for (int m = 0; m < MM; m++)
                if (mrow[m][k]) z[m] += e;
        }
#pragma unroll
        for (int m = 0; m < MM; m++) z[m] = warpSum(z[m]);
        if (lid == 0) {
#pragma unroll
            for (int m = 0; m < MM; m++) zred[wid][m] = z[m];
        }
        __syncthreads();
        float inv[MM];
#pragma unroll
        for (int m = 0; m < MM; m++) {
            float s = 0.f;
#pragma unroll
            for (int w = 0; w < 8; w++) s += zred[w][m];
            inv[m] = (1.0f / (float)MM) / s;
        }

        for (int k = tid; k < SS; k += 256) {
            float c = 0.f;
#pragma unroll
            for (int m = 0; m < MM; m++)
                if (mrow[m][k]) c += inv[m];
            float w = Erow[k] * c;
            __nv_bfloat16 h = __float2bfloat16_rn(w);
            hrow[k] = h;
            lrow[k] = __float2bfloat16_rn(w - __bfloat162float(h));
        }
        __syncthreads();
    }
}

// ---------------------------------------------------------------------------
extern "C" void kernel_launch(void* const* d_in, const int* in_sizes, int n_in,
                              void* d_out, int out_size)
{
    const float* x     = (const float*)d_in[0];
    const int*   masks = (const int*)  d_in[1];
    const float* Wq = (const float*)d_in[2]; const float* bq = (const float*)d_in[3];
    const float* Wk = (const float*)d_in[4]; /* bk: row-constant, drops in softmax */
    const float* Wv = (const float*)d_in[6]; const float* bv = (const float*)d_in[7];
    const float* Wo = (const float*)d_in[8]; const float* bo = (const float*)d_in[9];
    float* out = (float*)d_out;

    __nv_bfloat16 *xh, *xl, *sAh, *sAl, *sBh, *sBl, *sCh, *sCl;
    __nv_bfloat16 *Ph, *Pl, *Vth, *Vtl, *Sh, *Sl;
    float *Sc, *wkbq, *tau, *cbias;
    cudaGetSymbolAddress((void**)&xh, g_xh);     cudaGetSymbolAddress((void**)&xl, g_xl);
    cudaGetSymbolAddress((void**)&sAh, g_sAh);   cudaGetSymbolAddress((void**)&sAl, g_sAl);
    cudaGetSymbolAddress((void**)&sBh, g_sBh);   cudaGetSymbolAddress((void**)&sBl, g_sBl);
    cudaGetSymbolAddress((void**)&sCh, g_sCh);   cudaGetSymbolAddress((void**)&sCl, g_sCl);
    cudaGetSymbolAddress((void**)&Ph, g_Ph);     cudaGetSymbolAddress((void**)&Pl, g_Pl);
    cudaGetSymbolAddress((void**)&Vth, g_Vth);   cudaGetSymbolAddress((void**)&Vtl, g_Vtl);
    cudaGetSymbolAddress((void**)&Sc, g_S);
    cudaGetSymbolAddress((void**)&Sh, g_Sh);     cudaGetSymbolAddress((void**)&Sl, g_Sl);
    cudaGetSymbolAddress((void**)&wkbq, g_wkbq); cudaGetSymbolAddress((void**)&tau, g_tau);
    cudaGetSymbolAddress((void**)&cbias, g_cbias);

    cudaFuncSetAttribute(gemm3_kernel<0, false>, cudaFuncAttributeMaxDynamicSharedMemorySize, GEMM_SMEM_BYTES);
    cudaFuncSetAttribute(gemm3_kernel<0, true >, cudaFuncAttributeMaxDynamicSharedMemorySize, GEMM_SMEM_BYTES);
    cudaFuncSetAttribute(gemm3_kernel<1, false>, cudaFuncAttributeMaxDynamicSharedMemorySize, GEMM_SMEM_BYTES);

    const dim3 blk(256);
    const long long sdQKV = (long long)SS * DD;
    const long long sdS   = (long long)SS * SS;
    const long long sdVT  = (long long)DD * SS;
    const long long nw    = (long long)DD * DD;

    // 0. Splits + bias GEMVs
    {
        long long nx = (long long)BB * SS * DD;
        split_kernel<<<(unsigned)((nx / 4 + 255) / 256), blk>>>(x, xh, xl, nx);
        // small-GEMM A: z=0 Wk (row-major split), z=1 Wo^T (transpose split)
        split_kernel<<<(unsigned)((nw / 4 + 255) / 256), blk>>>(Wk, sAh, sAl, nw);
        dim3 tg(DD / 32, DD / 32, 1), tb(32, 8);
        split_transpose_kernel<<<tg, tb>>>(Wo, sAh + nw, sAl + nw, DD, DD);
        // small-GEMM B: z=0 Wq (row-major split), z=1 Wv (row-major split)
        split_kernel<<<(unsigned)((nw / 4 + 255) / 256), blk>>>(Wq, sBh, sBl, nw);
        split_kernel<<<(unsigned)((nw / 4 + 255) / 256), blk>>>(Wv, sBh + nw, sBl + nw, nw);
        wkbq_kernel<<<DD / 8, blk>>>(Wk, bq, wkbq);
        tau_kernel<<<(BB * SS) / 8, blk>>>(x, wkbq, tau);
        cbias_kernel<<<DD / 256, blk>>>(bv, Wo, bo, cbias);
    }

    // 1. Batched small GEMMs (z=0: Wqkt[d2][d1] = Wk@Wq^T ; z=1: Wvot[d3][d1] = Wo^T@Wv^T)
    {
        dim3 g(DD / BN, DD / BM, 2);
        gemm3_kernel<1, false><<<g, blk, GEMM_SMEM_BYTES>>>(sAh, sAl, sBh, sBl, nullptr,
            nullptr, sCh, sCl, DD, DD, DD, 1.0f, nw, nw, nw);
    }

    // 2. P = x @ Wqkt^T  -> bf16 hi/lo
    {
        dim3 g(DD / BN, (BB * SS) / BM, 1);
        gemm3_kernel<1, false><<<g, blk, GEMM_SMEM_BYTES>>>(xh, xl, sCh, sCl, nullptr,
            nullptr, Ph, Pl, BB * SS, DD, DD, 1.0f, 0, 0, 0);
    }

    // 3. Vt'[b] = Wvot @ x[b]^T  -> [B][D][S] bf16 hi/lo directly (batched z=4)
    {
        dim3 g(SS / BN, DD / BM, BB);
        gemm3_kernel<1, false><<<g, blk, GEMM_SMEM_BYTES>>>(sCh + nw, sCl + nw, xh, xl, nullptr,
            nullptr, Vth, Vtl, DD, SS, DD, 1.0f, 0, sdQKV, sdVT);
    }

    // 4. Scores: Sc[b] = P[b] @ x[b]^T / 32 (fp32 out)
    {
        dim3 g(SS / BN, SS / BM, BB);
        gemm3_kernel<0, false><<<g, blk, GEMM_SMEM_BYTES>>>(Ph, Pl, xh, xl, nullptr,
            Sc, nullptr, nullptr, SS, SS, DD, 0.03125f, sdQKV, sdQKV, sdS);
    }

    // 5. Multi-mask softmax combine (adds tau) -> bf16 hi/lo weights
    softmax_combine_kernel<<<SS, blk>>>(masks, Sc, tau, Sh, Sl);

    // 6. out[b] = W[b] @ Vt'[b]^T + cbias   (final output, fp32)
    {
        dim3 g(DD / BN, SS / BM, BB);
        gemm3_kernel<0, true><<<g, blk, GEMM_SMEM_BYTES>>>(Sh, Sl, Vth, Vtl, cbias,
            out, nullptr, nullptr, SS, DD, SS, 1.0f, sdS, sdVT, sdQKV);
    }
}

// round 15
// speedup vs baseline: 1.3166x; 1.0883x over previous
#include <cuda_runtime.h>
#include <cuda_bf16.h>
#include <cuda_fp16.h>
#include <cstdint>

// Problem constants
#define BB 4
#define SS 2048
#define DD 1024
#define MM 4

// GEMM tiling (proven): CTA 128x128, BK=32, 8 warps, 2-stage, SROW=40 pad
#define BM 128
#define BN 128
#define BK 32
#define SROW 40                 // halfwords per smem row (32 + 8 pad -> 80B)
#define TILEH (128 * SROW)      // halves per operand tile (10240 B)
#define NSTAGE 2
#define GEMM_SMEM_BYTES (NSTAGE * 4 * TILEH * 2)   // 81920
#define G2_SMEM_BYTES   (NSTAGE * 3 * TILEH * 2)   // 61440

#define WSCALE    16384.0f          // 2^14: lift softmax weights out of fp16 subnormal range
#define INV_WSCALE 6.103515625e-05f // 2^-14

// ---------------------------------------------------------------------------
// Scratch (__device__ globals; allocation-free rule)
// ---------------------------------------------------------------------------
__device__ __align__(256) __nv_bfloat16 g_xh[BB * SS * DD], g_xl[BB * SS * DD];
// small-GEMM combined operands: z=0 -> Wqkt inputs, z=1 -> Wvot inputs
__device__ __align__(256) __nv_bfloat16 g_sAh[2 * DD * DD], g_sAl[2 * DD * DD]; // [Wk ; Wo^T]
__device__ __align__(256) __nv_bfloat16 g_sBh[2 * DD * DD], g_sBl[2 * DD * DD]; // [Wq ; Wv]
__device__ __align__(256) __nv_bfloat16 g_sCh[2 * DD * DD], g_sCl[2 * DD * DD]; // [Wqkt ; Wvot]
__device__ __align__(256) __nv_bfloat16 g_Ph[BB * SS * DD], g_Pl[BB * SS * DD];  // P = x*Wqk
__device__ __align__(256) __half        g_VtH[BB * DD * SS], g_VtL[BB * DD * SS]; // (x Wvo)^T fp16
__device__ __align__(256) float         g_S[(long long)BB * SS * SS];
__device__ __align__(256) __half        g_Wt16[(long long)BB * SS * SS];   // scaled fp16 weights
__device__ __align__(256) float         g_wkbq[DD];        // Wk @ bq
__device__ __align__(256) float         g_tau[BB * SS];    // (x . wkbq)/32 per token
__device__ __align__(256) float         g_cbias[DD];       // bv @ Wo + bo

// ---------------------------------------------------------------------------
// PTX helpers
// ---------------------------------------------------------------------------
__device__ __forceinline__ void cp_async16(uint32_t saddr, const void* gptr) {
    asm volatile("cp.async.cg.shared.global [%0], [%1], 16;\n" :: "r"(saddr), "l"(gptr));
}
__device__ __forceinline__ void cp_commit() { asm volatile("cp.async.commit_group;\n"); }
__device__ __forceinline__ void cp_wait1()  { asm volatile("cp.async.wait_group 1;\n"); }
__device__ __forceinline__ void ldsm4(uint32_t* r, uint32_t saddr) {
    asm volatile("ldmatrix.sync.aligned.m8n8.x4.shared.b16 {%0,%1,%2,%3}, [%4];\n"
                 : "=r"(r[0]), "=r"(r[1]), "=r"(r[2]), "=r"(r[3]) : "r"(saddr));
}
__device__ __forceinline__ void mma_bf16(float* c, const uint32_t* a, const uint32_t* b) {
    asm volatile(
        "mma.sync.aligned.m16n8k16.row.col.f32.bf16.bf16.f32 "
        "{%0,%1,%2,%3}, {%4,%5,%6,%7}, {%8,%9}, {%0,%1,%2,%3};\n"
        : "+f"(c[0]), "+f"(c[1]), "+f"(c[2]), "+f"(c[3])
        : "r"(a[0]), "r"(a[1]), "r"(a[2]), "r"(a[3]), "r"(b[0]), "r"(b[1]));
}
__device__ __forceinline__ void mma_f16(float* c, const uint32_t* a, const uint32_t* b) {
    asm volatile(
        "mma.sync.aligned.m16n8k16.row.col.f32.f16.f16.f32 "
        "{%0,%1,%2,%3}, {%4,%5,%6,%7}, {%8,%9}, {%0,%1,%2,%3};\n"
        : "+f"(c[0]), "+f"(c[1]), "+f"(c[2]), "+f"(c[3])
        : "r"(a[0]), "r"(a[1]), "r"(a[2]), "r"(a[3]), "r"(b[0]), "r"(b[1]));
}

// ---------------------------------------------------------------------------
// 3-term split-bf16 GEMM (proven): C = scale * A @ B^T (+ bias)
// EPI=0: fp32 C.  EPI=1: bf16 hi/lo outputs.  EPI=2: fp16 hi/lo outputs
// (Chi/Clo reinterpreted as __half*).  Batched via blockIdx.z.
// ---------------------------------------------------------------------------
template <int EPI, bool BIAS>
__global__ void __launch_bounds__(256) gemm3_kernel(
    const __nv_bfloat16* __restrict__ Ah, const __nv_bfloat16* __restrict__ Al,
    const __nv_bfloat16* __restrict__ Bh, const __nv_bfloat16* __restrict__ Bl,
    const float* __restrict__ bias,
    float* __restrict__ C, __nv_bfloat16* __restrict__ Chi, __nv_bfloat16* __restrict__ Clo,
    int Mdim, int Ndim, int Kdim, float scale,
    long long sA, long long sB, long long sC)
{
    Ah += (long long)blockIdx.z * sA;  Al += (long long)blockIdx.z * sA;
    Bh += (long long)blockIdx.z * sB;  Bl += (long long)blockIdx.z * sB;
    if (EPI == 0) C += (long long)blockIdx.z * sC;
    else { Chi += (long long)blockIdx.z * sC; Clo += (long long)blockIdx.z * sC; }

    extern __shared__ __align__(16) __nv_bfloat16 smem[];
    const uint32_t smem_u32 = (uint32_t)__cvta_generic_to_shared(smem);

    const int tid  = threadIdx.x;
    const int lane = tid & 31;
    const int warp = tid >> 5;
    const int wm = warp >> 2;
    const int wn = warp & 3;
    const int m0 = blockIdx.y * BM;
    const int n0 = blockIdx.x * BN;

    const int aRow = lane & 15;
    const int aK   = (lane >> 4) << 3;
    const int bRow = (((lane >> 4) & 1) << 3) + (lane & 7);
    const int bK   = ((lane >> 3) & 1) << 3;

    float acc[4][4][4];
#pragma unroll
    for (int i = 0; i < 4; i++)
#pragma unroll
        for (int j = 0; j < 4; j++)
#pragma unroll
            for (int c = 0; c < 4; c++) acc[i][j][c] = 0.f;

    const int tiles = Kdim / BK;

    auto load_stage = [&](int st, int k0) {
        uint32_t sbase = smem_u32 + (uint32_t)(st * 4 * TILEH * 2);
#pragma unroll
        for (int p = 0; p < 2; p++) {
            int idx = tid + p * 256;
            int row = idx >> 2;
            int kc  = (idx & 3) << 3;
            long long ga = (long long)(m0 + row) * Kdim + k0 + kc;
            long long gb = (long long)(n0 + row) * Kdim + k0 + kc;
            uint32_t so = (uint32_t)((row * SROW + kc) * 2);
            cp_async16(sbase + 0 * TILEH * 2 + so, Ah + ga);
            cp_async16(sbase + 1 * TILEH * 2 + so, Al + ga);
            cp_async16(sbase + 2 * TILEH * 2 + so, Bh + gb);
            cp_async16(sbase + 3 * TILEH * 2 + so, Bl + gb);
        }
    };

    load_stage(0, 0);
    cp_commit();

    for (int t = 0; t < tiles; ++t) {
        const int st = t & 1;
        if (t + 1 < tiles) load_stage(st ^ 1, (t + 1) * BK);
        cp_commit();
        cp_wait1();
        __syncthreads();

        const uint32_t sbase = smem_u32 + (uint32_t)(st * 4 * TILEH * 2);
        const uint32_t sAh = sbase;
        const uint32_t sAl = sbase + 1u * TILEH * 2;
        const uint32_t sBh = sbase + 2u * TILEH * 2;
        const uint32_t sBl = sbase + 3u * TILEH * 2;

#pragma unroll
        for (int k16 = 0; k16 < 2; ++k16) {
            const int kb = k16 * 16;
            uint32_t a[4][4], bh[4][2], bl[4][2];

#pragma unroll
            for (int h = 0; h < 2; h++) {
                uint32_t off = (uint32_t)(((wn * 32 + h * 16 + bRow) * SROW + kb + bK) * 2);
                uint32_t r[4];
                ldsm4(r, sBh + off);
                bh[2 * h][0] = r[0]; bh[2 * h][1] = r[1];
                bh[2 * h + 1][0] = r[2]; bh[2 * h + 1][1] = r[3];
                ldsm4(r, sBl + off);
                bl[2 * h][0] = r[0]; bl[2 * h][1] = r[1];
                bl[2 * h + 1][0] = r[2]; bl[2 * h + 1][1] = r[3];
            }

#pragma unroll
            for (int mt = 0; mt < 4; mt++) {
                uint32_t off = (uint32_t)(((wm * 64 + mt * 16 + aRow) * SROW + kb + aK) * 2);
                ldsm4(a[mt], sAh + off);
            }
#pragma unroll
            for (int mt = 0; mt < 4; mt++)
#pragma unroll
                for (int nt = 0; nt < 4; nt++) mma_bf16(acc[mt][nt], a[mt], bh[nt]);
#pragma unroll
            for (int mt = 0; mt < 4; mt++)
#pragma unroll
                for (int nt = 0; nt < 4; nt++) mma_bf16(acc[mt][nt], a[mt], bl[nt]);

#pragma unroll
            for (int mt = 0; mt < 4; mt++) {
                uint32_t off = (uint32_t)(((wm * 64 + mt * 16 + aRow) * SROW + kb + aK) * 2);
                ldsm4(a[mt], sAl + off);
            }
#pragma unroll
            for (int mt = 0; mt < 4; mt++)
#pragma unroll
                for (int nt = 0; nt < 4; nt++) mma_bf16(acc[mt][nt], a[mt], bh[nt]);
        }
        __syncthreads();
    }

    const int g  = lane >> 2;
    const int tg = lane & 3;
#pragma unroll
    for (int mt = 0; mt < 4; mt++) {
#pragma unroll
        for (int nt = 0; nt < 4; nt++) {
            int row = m0 + wm * 64 + mt * 16 + g;
            int col = n0 + wn * 32 + nt * 8 + tg * 2;
            float b0 = 0.f, b1 = 0.f;
            if (BIAS) { b0 = bias[col]; b1 = bias[col + 1]; }
            float v0 = acc[mt][nt][0] * scale + b0;
            float v1 = acc[mt][nt][1] * scale + b1;
            float v2 = acc[mt][nt][2] * scale + b0;
            float v3 = acc[mt][nt][3] * scale + b1;
            if (EPI == 0) {
                *reinterpret_cast<float2*>(C + (long long)row * Ndim + col)       = make_float2(v0, v1);
                *reinterpret_cast<float2*>(C + (long long)(row + 8) * Ndim + col) = make_float2(v2, v3);
            } else if (EPI == 1) {
                __nv_bfloat16 h0 = __float2bfloat16_rn(v0);
                __nv_bfloat16 h1 = __float2bfloat16_rn(v1);
                __nv_bfloat16 h2 = __float2bfloat16_rn(v2);
                __nv_bfloat16 h3 = __float2bfloat16_rn(v3);
                __nv_bfloat16 l0 = __float2bfloat16_rn(v0 - __bfloat162float(h0));
                __nv_bfloat16 l1 = __float2bfloat16_rn(v1 - __bfloat162float(h1));
                __nv_bfloat16 l2 = __float2bfloat16_rn(v2 - __bfloat162float(h2));
                __nv_bfloat16 l3 = __float2bfloat16_rn(v3 - __bfloat162float(h3));
                *reinterpret_cast<__nv_bfloat162*>(Chi + (long long)row * Ndim + col)       = __nv_bfloat162(h0, h1);
                *reinterpret_cast<__nv_bfloat162*>(Chi + (long long)(row + 8) * Ndim + col) = __nv_bfloat162(h2, h3);
                *reinterpret_cast<__nv_bfloat162*>(Clo + (long long)row * Ndim + col)       = __nv_bfloat162(l0, l1);
                *reinterpret_cast<__nv_bfloat162*>(Clo + (long long)(row + 8) * Ndim + col) = __nv_bfloat162(l2, l3);
            } else {
                __half* ChiH = reinterpret_cast<__half*>(Chi);
                __half* CloH = reinterpret_cast<__half*>(Clo);
                __half h0 = __float2half_rn(v0);
                __half h1 = __float2half_rn(v1);
                __half h2 = __float2half_rn(v2);
                __half h3 = __float2half_rn(v3);
                __half l0 = __float2half_rn(v0 - __half2float(h0));
                __half l1 = __float2half_rn(v1 - __half2float(h1));
                __half l2 = __float2half_rn(v2 - __half2float(h2));
                __half l3 = __float2half_rn(v3 - __half2float(h3));
                *reinterpret_cast<__half2*>(ChiH + (long long)row * Ndim + col)       = __halves2half2(h0, h1);
                *reinterpret_cast<__half2*>(ChiH + (long long)(row + 8) * Ndim + col) = __halves2half2(h2, h3);
                *reinterpret_cast<__half2*>(CloH + (long long)row * Ndim + col)       = __halves2half2(l0, l1);
                *reinterpret_cast<__half2*>(CloH + (long long)(row + 8) * Ndim + col) = __halves2half2(l2, l3);
            }
        }
    }
}

// ---------------------------------------------------------------------------
// 2-pass fp16 GEMM: C = scale * A @ B^T + bias
//   A: fp16 hi only [M][K] k-major.  B: Bh+Bl fp16 [N][K] k-major.
//   computes Ah*Bh + Ah*Bl, fp32 accum, fp32 C.  Batched via blockIdx.z.
// ---------------------------------------------------------------------------
template <bool BIAS>
__global__ void __launch_bounds__(256) gemm2h_kernel(
    const __half* __restrict__ Ah,
    const __half* __restrict__ Bh, const __half* __restrict__ Bl,
    const float* __restrict__ bias, float* __restrict__ C,
    int Ndim, int Kdim, float scale,
    long long sA, long long sB, long long sC)
{
    Ah += (long long)blockIdx.z * sA;
    Bh += (long long)blockIdx.z * sB;  Bl += (long long)blockIdx.z * sB;
    C  += (long long)blockIdx.z * sC;

    extern __shared__ __align__(16) __half smemh[];
    const uint32_t smem_u32 = (uint32_t)__cvta_generic_to_shared(smemh);

    const int tid  = threadIdx.x;
    const int lane = tid & 31;
    const int warp = tid >> 5;
    const int wm = warp >> 2;
    const int wn = warp & 3;
    const int m0 = blockIdx.y * BM;
    const int n0 = blockIdx.x * BN;

    const int aRow = lane & 15;
    const int aK   = (lane >> 4) << 3;
    const int bRow = (((lane >> 4) & 1) << 3) + (lane & 7);
    const int bK   = ((lane >> 3) & 1) << 3;

    float acc[4][4][4];
#pragma unroll
    for (int i = 0; i < 4; i++)
#pragma unroll
        for (int j = 0; j < 4; j++)
#pragma unroll
            for (int c = 0; c < 4; c++) acc[i][j][c] = 0.f;

    const int tiles = Kdim / BK;

    auto load_stage = [&](int st, int k0) {
        uint32_t sbase = smem_u32 + (uint32_t)(st * 3 * TILEH * 2);
#pragma unroll
        for (int p = 0; p < 2; p++) {
            int idx = tid + p * 256;
            int row = idx >> 2;
            int kc  = (idx & 3) << 3;
            long long ga = (long long)(m0 + row) * Kdim + k0 + kc;
            long long gb = (long long)(n0 + row) * Kdim + k0 + kc;
            uint32_t so = (uint32_t)((row * SROW + kc) * 2);
            cp_async16(sbase + 0 * TILEH * 2 + so, Ah + ga);
            cp_async16(sbase + 1 * TILEH * 2 + so, Bh + gb);
            cp_async16(sbase + 2 * TILEH * 2 + so, Bl + gb);
        }
    };

    load_stage(0, 0);
    cp_commit();

    for (int t = 0; t < tiles; ++t) {
        const int st = t & 1;
        if (t + 1 < tiles) load_stage(st ^ 1, (t + 1) * BK);
        cp_commit();
        cp_wait1();
        __syncthreads();

        const uint32_t sbase = smem_u32 + (uint32_t)(st * 3 * TILEH * 2);
        const uint32_t sAh = sbase;
        const uint32_t sBh = sbase + 1u * TILEH * 2;
        const uint32_t sBl = sbase + 2u * TILEH * 2;

#pragma unroll
        for (int k16 = 0; k16 < 2; ++k16) {
            const int kb = k16 * 16;
            uint32_t a[4][4], bh[4][2], bl[4][2];

#pragma unroll
            for (int h = 0; h < 2; h++) {
                uint32_t off = (uint32_t)(((wn * 32 + h * 16 + bRow) * SROW + kb + bK) * 2);
                uint32_t r[4];
                ldsm4(r, sBh + off);
                bh[2 * h][0] = r[0]; bh[2 * h][1] = r[1];
                bh[2 * h + 1][0] = r[2]; bh[2 * h + 1][1] = r[3];
                ldsm4(r, sBl + off);
                bl[2 * h][0] = r[0]; bl[2 * h][1] = r[1];
                bl[2 * h + 1][0] = r[2]; bl[2 * h + 1][1] = r[3];
            }
#pragma unroll
            for (int mt = 0; mt < 4; mt++) {
                uint32_t off = (uint32_t)(((wm * 64 + mt * 16 + aRow) * SROW + kb + aK) * 2);
                ldsm4(a[mt], sAh + off);
            }
#pragma unroll
            for (int mt = 0; mt < 4; mt++)
#pragma unroll
                for (int nt = 0; nt < 4; nt++) mma_f16(acc[mt][nt], a[mt], bh[nt]);
#pragma unroll
            for (int mt = 0; mt < 4; mt++)
#pragma unroll
                for (int nt = 0; nt < 4; nt++) mma_f16(acc[mt][nt], a[mt], bl[nt]);
        }
        __syncthreads();
    }

    const int g  = lane >> 2;
    const int tg = lane & 3;
#pragma unroll
    for (int mt = 0; mt < 4; mt++) {
#pragma unroll
        for (int nt = 0; nt < 4; nt++) {
            int row = m0 + wm * 64 + mt * 16 + g;
            int col = n0 + wn * 32 + nt * 8 + tg * 2;
            float b0 = 0.f, b1 = 0.f;
            if (BIAS) { b0 = bias[col]; b1 = bias[col + 1]; }
            *reinterpret_cast<float2*>(C + (long long)row * Ndim + col) =
                make_float2(acc[mt][nt][0] * scale + b0, acc[mt][nt][1] * scale + b1);
            *reinterpret_cast<float2*>(C + (long long)(row + 8) * Ndim + col) =
                make_float2(acc[mt][nt][2] * scale + b0, acc[mt][nt][3] * scale + b1);
        }
    }
}

// ---------------------------------------------------------------------------
// fp32 -> bf16 hi/lo elementwise split
// ---------------------------------------------------------------------------
__global__ void __launch_bounds__(256) split_kernel(
    const float* __restrict__ src, __nv_bfloat16* __restrict__ hi,
    __nv_bfloat16* __restrict__ lo, long long n)
{
    long long i = ((long long)blockIdx.x * 256 + threadIdx.x) * 4;
    if (i >= n) return;
    float4 v = *reinterpret_cast<const float4*>(src + i);
    __nv_bfloat16 h0 = __float2bfloat16_rn(v.x), h1 = __float2bfloat16_rn(v.y);
    __nv_bfloat16 h2 = __float2bfloat16_rn(v.z), h3 = __float2bfloat16_rn(v.w);
    __nv_bfloat16 l0 = __float2bfloat16_rn(v.x - __bfloat162float(h0));
    __nv_bfloat16 l1 = __float2bfloat16_rn(v.y - __bfloat162float(h1));
    __nv_bfloat16 l2 = __float2bfloat16_rn(v.z - __bfloat162float(h2));
    __nv_bfloat16 l3 = __float2bfloat16_rn(v.w - __bfloat162float(h3));
    __nv_bfloat162* ph = reinterpret_cast<__nv_bfloat162*>(hi + i);
    __nv_bfloat162* pl = reinterpret_cast<__nv_bfloat162*>(lo + i);
    ph[0] = __nv_bfloat162(h0, h1); ph[1] = __nv_bfloat162(h2, h3);
    pl[0] = __nv_bfloat162(l0, l1); pl[1] = __nv_bfloat162(l2, l3);
}

// ---------------------------------------------------------------------------
// fp32 [R][C] -> transposed bf16 hi/lo [C][R]
// ---------------------------------------------------------------------------
__global__ void __launch_bounds__(256) split_transpose_kernel(
    const float* __restrict__ src, __nv_bfloat16* __restrict__ hi,
    __nv_bfloat16* __restrict__ lo, int R, int C)
{
    __shared__ float t[32][33];
    const long long inb  = (long long)blockIdx.z * R * C;
    const long long outb = (long long)blockIdx.z * C * R;
    const int tx = threadIdx.x, ty = threadIdx.y;
    const int r0 = blockIdx.y * 32, c0 = blockIdx.x * 32;

#pragma unroll
    for (int j = 0; j < 4; j++)
        t[ty + j * 8][tx] = src[inb + (long long)(r0 + ty + j * 8) * C + c0 + tx];
    __syncthreads();
#pragma unroll
    for (int j = 0; j < 4; j++) {
        float v = t[tx][ty + j * 8];
        __nv_bfloat16 h = __float2bfloat16_rn(v);
        __nv_bfloat16 l = __float2bfloat16_rn(v - __bfloat162float(h));
        long long o = outb + (long long)(c0 + ty + j * 8) * R + r0 + tx;
        hi[o] = h; lo[o] = l;
    }
}

// ---------------------------------------------------------------------------
// Bias helpers
// ---------------------------------------------------------------------------
__global__ void __launch_bounds__(256) wkbq_kernel(
    const float* __restrict__ Wk, const float* __restrict__ bq, float* __restrict__ wkbq)
{
    const int warp = threadIdx.x >> 5, lane = threadIdx.x & 31;
    const int row = blockIdx.x * 8 + warp;
    if (row >= DD) return;
    const float* wrow = Wk + (long long)row * DD;
    float s = 0.f;
    for (int j = lane; j < DD; j += 32) s = fmaf(wrow[j], bq[j], s);
#pragma unroll
    for (int o = 16; o > 0; o >>= 1) s += __shfl_xor_sync(0xffffffffu, s, o);
    if (lane == 0) wkbq[row] = s;
}

__global__ void __launch_bounds__(256) tau_kernel(
    const float* __restrict__ x, const float* __restrict__ wkbq, float* __restrict__ tau)
{
    const int warp = threadIdx.x >> 5, lane = threadIdx.x & 31;
    const int row = blockIdx.x * 8 + warp;
    if (row >= BB * SS) return;
    const float* xrow = x + (long long)row * DD;
    float s = 0.f;
    for (int j = lane; j < DD; j += 32) s = fmaf(xrow[j], wkbq[j], s);
#pragma unroll
    for (int o = 16; o > 0; o >>= 1) s += __shfl_xor_sync(0xffffffffu, s, o);
    if (lane == 0) tau[row] = s * 0.03125f;
}

__global__ void __launch_bounds__(256) cbias_kernel(
    const float* __restrict__ bv, const float* __restrict__ Wo,
    const float* __restrict__ bo, float* __restrict__ cbias)
{
    const int d3 = blockIdx.x * 256 + threadIdx.x;
    if (d3 >= DD) return;
    float s = bo[d3];
    for (int j = 0; j < DD; j++) s = fmaf(bv[j], Wo[(long long)j * DD + d3], s);
    cbias[d3] = s;
}

// ---------------------------------------------------------------------------
// Fast exp on the FMA pipe (no MUFU). Valid for softmax args (x <= 0).
// ---------------------------------------------------------------------------
__device__ __forceinline__ float fast_exp(float x) {
    float y = x * 1.4426950408889634f;
    y = fmaxf(y, -126.0f);
    float t = y + 12582912.0f;
    int   ni = __float_as_int(t) - 0x4B400000;
    float f = y - (t - 12582912.0f);
    float p = 1.3333558146e-3f;
    p = fmaf(p, f, 9.6181291076e-3f);
    p = fmaf(p, f, 5.5504108664e-2f);
    p = fmaf(p, f, 2.4022650696e-1f);
    p = fmaf(p, f, 6.9314718056e-1f);
    p = fmaf(p, f, 1.0f);
    return __int_as_float(__float_as_int(p) + (ni << 23));
}

// ---------------------------------------------------------------------------
// Fused multi-mask softmax combine: scores + tau -> scaled fp16 weights
// ---------------------------------------------------------------------------
__device__ __forceinline__ float warpMax(float v) {
#pragma unroll
    for (int o = 16; o > 0; o >>= 1) v = fmaxf(v, __shfl_xor_sync(0xffffffffu, v, o));
    return v;
}
__device__ __forceinline__ float warpSum(float v) {
#pragma unroll
    for (int o = 16; o > 0; o >>= 1) v += __shfl_xor_sync(0xffffffffu, v, o);
    return v;
}

__global__ void __launch_bounds__(256) softmax_combine_kernel(
    const int* __restrict__ masks, const float* __restrict__ Sc,
    const float* __restrict__ tau, __half* __restrict__ Wh)
{
    const int q   = blockIdx.x;
    const int tid = threadIdx.x;
    const int wid = tid >> 5;
    const int lid = tid & 31;

    __shared__ float         Erow[SS];
    __shared__ unsigned char mrow[MM][SS];
    __shared__ float         mred[8];
    __shared__ float         zred[8][MM];

#pragma unroll
    for (int m = 0; m < MM; m++) {
        const int* mp = masks + ((long long)m * SS + q) * SS;
        for (int k = tid; k < SS; k += 256) mrow[m][k] = (unsigned char)mp[k];
    }
    __syncthreads();

    for (int b = 0; b < BB; b++) {
        const float* srow = Sc + ((long long)b * SS + q) * SS;
        const float* trow = tau + (long long)b * SS;
        __half* hrow = Wh + ((long long)b * SS + q) * SS;

        float mx = -1e30f;
        for (int k = tid; k < SS; k += 256) {
            float v = srow[k] + trow[k];
            Erow[k] = v;
            mx = fmaxf(mx, v);
        }
        mx = warpMax(mx);
        if (lid == 0) mred[wid] = mx;
        __syncthreads();
        mx = mred[0];
#pragma unroll
        for (int w = 1; w < 8; w++) mx = fmaxf(mx, mred[w]);

        float z[MM] = {0.f, 0.f, 0.f, 0.f};
        for (int k = tid; k < SS; k += 256) {
            float e = fast_exp(Erow[k] - mx);
            Erow[k] = e;
#pragma unroll
            for (int m = 0; m < MM; m++)
                if (mrow[m][k]) z[m] += e;
        }
#pragma unroll
        for (int m = 0; m < MM; m++) z[m] = warpSum(z[m]);
        if (lid == 0) {
#pragma unroll
            for (int m = 0; m < MM; m++) zred[wid][m] = z[m];
        }
        __syncthreads();
        float inv[MM];
#pragma unroll
        for (int m = 0; m < MM; m++) {
            float s = 0.f;
#pragma unroll
            for (int w = 0; w < 8; w++) s += zred[w][m];
            inv[m] = (WSCALE / (float)MM) / s;   // fold /M and the 2^14 fp16 lift
        }

        for (int k = tid; k < SS; k += 256) {
            float c = 0.f;
#pragma unroll
            for (int m = 0; m < MM; m++)
                if (mrow[m][k]) c += inv[m];
            hrow[k] = __float2half_rn(Erow[k] * c);
        }
        __syncthreads();
    }
}

// ---------------------------------------------------------------------------
extern "C" void kernel_launch(void* const* d_in, const int* in_sizes, int n_in,
                              void* d_out, int out_size)
{
    const float* x     = (const float*)d_in[0];
    const int*   masks = (const int*)  d_in[1];
    const float* Wq = (const float*)d_in[2]; const float* bq = (const float*)d_in[3];
    const float* Wk = (const float*)d_in[4]; /* bk: row-constant, drops in softmax */
    const float* Wv = (const float*)d_in[6]; const float* bv = (const float*)d_in[7];
    const float* Wo = (const float*)d_in[8]; const float* bo = (const float*)d_in[9];
    float* out = (float*)d_out;

    __nv_bfloat16 *xh, *xl, *sAh, *sAl, *sBh, *sBl, *sCh, *sCl, *Ph, *Pl;
    __half *VtH, *VtL, *Wt16;
    float *Sc, *wkbq, *tau, *cbias;
    cudaGetSymbolAddress((void**)&xh, g_xh);     cudaGetSymbolAddress((void**)&xl, g_xl);
    cudaGetSymbolAddress((void**)&sAh, g_sAh);   cudaGetSymbolAddress((void**)&sAl, g_sAl);
    cudaGetSymbolAddress((void**)&sBh, g_sBh);   cudaGetSymbolAddress((void**)&sBl, g_sBl);
    cudaGetSymbolAddress((void**)&sCh, g_sCh);   cudaGetSymbolAddress((void**)&sCl, g_sCl);
    cudaGetSymbolAddress((void**)&Ph, g_Ph);     cudaGetSymbolAddress((void**)&Pl, g_Pl);
    cudaGetSymbolAddress((void**)&VtH, g_VtH);   cudaGetSymbolAddress((void**)&VtL, g_VtL);
    cudaGetSymbolAddress((void**)&Sc, g_S);
    cudaGetSymbolAddress((void**)&Wt16, g_Wt16);
    cudaGetSymbolAddress((void**)&wkbq, g_wkbq); cudaGetSymbolAddress((void**)&tau, g_tau);
    cudaGetSymbolAddress((void**)&cbias, g_cbias);

    cudaFuncSetAttribute(gemm3_kernel<0, false>, cudaFuncAttributeMaxDynamicSharedMemorySize, GEMM_SMEM_BYTES);
    cudaFuncSetAttribute(gemm3_kernel<1, false>, cudaFuncAttributeMaxDynamicSharedMemorySize, GEMM_SMEM_BYTES);
    cudaFuncSetAttribute(gemm3_kernel<2, false>, cudaFuncAttributeMaxDynamicSharedMemorySize, GEMM_SMEM_BYTES);
    cudaFuncSetAttribute(gemm2h_kernel<true>,    cudaFuncAttributeMaxDynamicSharedMemorySize, G2_SMEM_BYTES);

    const dim3 blk(256);
    const long long sdQKV = (long long)SS * DD;
    const long long sdS   = (long long)SS * SS;
    const long long sdVT  = (long long)DD * SS;
    const long long nw    = (long long)DD * DD;

    // 0. Splits + bias GEMVs
    {
        long long nx = (long long)BB * SS * DD;
        split_kernel<<<(unsigned)((nx / 4 + 255) / 256), blk>>>(x, xh, xl, nx);
        split_kernel<<<(unsigned)((nw / 4 + 255) / 256), blk>>>(Wk, sAh, sAl, nw);
        dim3 tg(DD / 32, DD / 32, 1), tb(32, 8);
        split_transpose_kernel<<<tg, tb>>>(Wo, sAh + nw, sAl + nw, DD, DD);
        split_kernel<<<(unsigned)((nw / 4 + 255) / 256), blk>>>(Wq, sBh, sBl, nw);
        split_kernel<<<(unsigned)((nw / 4 + 255) / 256), blk>>>(Wv, sBh + nw, sBl + nw, nw);
        wkbq_kernel<<<DD / 8, blk>>>(Wk, bq, wkbq);
        tau_kernel<<<(BB * SS) / 8, blk>>>(x, wkbq, tau);
        cbias_kernel<<<DD / 256, blk>>>(bv, Wo, bo, cbias);
    }

    // 1. Batched small GEMMs (z=0: Wqkt = Wk@Wq^T ; z=1: Wvot = Wo^T@Wv^T)
    {
        dim3 g(DD / BN, DD / BM, 2);
        gemm3_kernel<1, false><<<g, blk, GEMM_SMEM_BYTES>>>(sAh, sAl, sBh, sBl, nullptr,
            nullptr, sCh, sCl, DD, DD, DD, 1.0f, nw, nw, nw);
    }

    // 2. P = x @ Wqkt^T  -> bf16 hi/lo
    {
        dim3 g(DD / BN, (BB * SS) / BM, 1);
        gemm3_kernel<1, false><<<g, blk, GEMM_SMEM_BYTES>>>(xh, xl, sCh, sCl, nullptr,
            nullptr, Ph, Pl, BB * SS, DD, DD, 1.0f, 0, 0, 0);
    }

    // 3. Vt'[b] = Wvot @ x[b]^T  -> [B][D][S] fp16 hi/lo (EPI=2)
    {
        dim3 g(SS / BN, DD / BM, BB);
        gemm3_kernel<2, false><<<g, blk, GEMM_SMEM_BYTES>>>(sCh + nw, sCl + nw, xh, xl, nullptr,
            nullptr, (__nv_bfloat16*)VtH, (__nv_bfloat16*)VtL, DD, SS, DD, 1.0f, 0, sdQKV, sdVT);
    }

    // 4. Scores: Sc[b] = P[b] @ x[b]^T / 32 (fp32 out, bf16 3-pass)
    {
        dim3 g(SS / BN, SS / BM, BB);
        gemm3_kernel<0, false><<<g, blk, GEMM_SMEM_BYTES>>>(Ph, Pl, xh, xl, nullptr,
            Sc, nullptr, nullptr, SS, SS, DD, 0.03125f, sdQKV, sdQKV, sdS);
    }

    // 5. Multi-mask softmax combine (adds tau) -> fp16 weights scaled by 2^14
    softmax_combine_kernel<<<SS, blk>>>(masks, Sc, tau, Wt16);

    // 6. out[b] = 2^-14 * (Wt16[b] @ Vt'[b]^T) + cbias   (fp16 2-pass)
    {
        dim3 g(DD / BN, SS / BM, BB);
        gemm2h_kernel<true><<<g, blk, G2_SMEM_BYTES>>>(Wt16, VtH, VtL, cbias,
            out, DD, SS, INV_WSCALE, sdS, sdVT, sdQKV);
    }
}